// round 8
// baseline (speedup 1.0000x reference)
#include <cuda_runtime.h>
#include <cuda_bf16.h>
#include <cstdint>
#include <cstddef>

// ---------------------------------------------------------------------------
// SelectiveViTAdapter: LN(q), LN(f) -> MSDeformAttn -> gamma residual -> stable
// mask-descending sort gather.
// GEMMs: ldmatrix + mma.sync m16n8k16 bf16 (fp32 acc), cp.async double-buffer.
// value stored bf16; residual+scatter fused into the out-GEMM epilogue.
// No tcgen05 / no mbarrier / static smem only.
// ---------------------------------------------------------------------------

#define BATCH 8
#define DMODEL 768
#define NHEAD 6
#define DHEAD 128
#define LQ 1024
#define LIN 5376
#define NQROWS (BATCH * LQ)      // 8192
#define NFROWS (BATCH * LIN)     // 43008
#define OFFCOLS 144
#define ATTNCOLS 72
#define OFF_LD 256
#define ATT_LD 128

// -------------------- scratch (static device globals) ----------------------
__device__ __nv_bfloat16 g_qbf[NQROWS * DMODEL];
__device__ __nv_bfloat16 g_fbf[NFROWS * DMODEL];
__device__ __nv_bfloat16 g_valueb[NFROWS * DMODEL];
__device__ float         g_off[NQROWS * OFF_LD];
__device__ float         g_attnlog[NQROWS * ATT_LD];
__device__ __nv_bfloat16 g_sampb[NQROWS * DMODEL];
__device__ int           g_dest[NQROWS];
__device__ __nv_bfloat16 g_wvalT[DMODEL * DMODEL];
__device__ __nv_bfloat16 g_woutT[DMODEL * DMODEL];
__device__ __nv_bfloat16 g_woffT[OFF_LD * DMODEL];
__device__ __nv_bfloat16 g_wattnT[ATT_LD * DMODEL];

// -------------------- PTX helpers ------------------------------------------
__device__ __forceinline__ uint32_t smem_u32(const void* p) {
    uint32_t a;
    asm("{ .reg .u64 t; cvta.to.shared.u64 t, %1; cvt.u32.u64 %0, t; }" : "=r"(a) : "l"(p));
    return a;
}
#define CP_ASYNC16(dst, src) asm volatile("cp.async.cg.shared.global [%0], [%1], 16;" :: "r"(dst), "l"(src) : "memory")
#define CP_COMMIT()          asm volatile("cp.async.commit_group;" ::: "memory")
#define CP_WAIT(n)           asm volatile("cp.async.wait_group %0;" :: "n"(n) : "memory")
#define LDSM4(r, a) asm volatile("ldmatrix.sync.aligned.m8n8.x4.shared.b16 {%0,%1,%2,%3}, [%4];" \
    : "=r"((r)[0]), "=r"((r)[1]), "=r"((r)[2]), "=r"((r)[3]) : "r"(a))

__device__ __forceinline__ void mma16816(float* c, const uint32_t* a, uint32_t b0, uint32_t b1) {
    asm volatile(
        "mma.sync.aligned.m16n8k16.row.col.f32.bf16.bf16.f32 "
        "{%0,%1,%2,%3}, {%4,%5,%6,%7}, {%8,%9}, {%0,%1,%2,%3};"
        : "+f"(c[0]), "+f"(c[1]), "+f"(c[2]), "+f"(c[3])
        : "r"(a[0]), "r"(a[1]), "r"(a[2]), "r"(a[3]), "r"(b0), "r"(b1));
}

// Swizzled smem offset for [rows x 32 bf16] tiles (64B rows, 16B chunks).
__device__ __forceinline__ uint32_t sw_off(int r, int c) {
    return (uint32_t)(r * 64 + ((c ^ ((r >> 1) & 3)) << 4));
}

// -------------------- bf16 tensor-core GEMM --------------------------------
// MODE 0: C f32 = A@Bt^T + bias (ldc stride, Nreal guard on bias)
// MODE 1: C bf16 = A@Bt^T + bias (value GEMM)
// MODE 2: fused: out[dest-row] f32 = query[row] + gamma*(acc + bias)
// Mainloop identical to the round-6 passing kernel.
template <int MODE>
__global__ __launch_bounds__(256) void mma_gemm(
    const __nv_bfloat16* __restrict__ A, const __nv_bfloat16* __restrict__ Bt,
    const float* __restrict__ bias, void* __restrict__ Cv,
    int Nreal, int ldc,
    const float* __restrict__ query, const float* __restrict__ gamma,
    const int* __restrict__ dest) {
    __shared__ __align__(128) char smbuf[2 * 16384];   // stage: A 8K + B 8K
    uint32_t sb = smem_u32(smbuf);
    int tid = threadIdx.x, wid = tid >> 5, lane = tid & 31;
    int m0 = blockIdx.y * 128, n0 = blockIdx.x * 128;
    int wm = (wid >> 2) * 64, wn = (wid & 3) * 32;

    const __nv_bfloat16* Ag = A + (size_t)m0 * DMODEL;
    const __nv_bfloat16* Bg = Bt + (size_t)n0 * DMODEL;

    int lr0 = tid >> 2, lc = tid & 3;
    int lr1 = lr0 + 64;
    uint32_t dA0 = sw_off(lr0, lc), dA1 = sw_off(lr1, lc);

    float acc[4][4][4];
    #pragma unroll
    for (int i = 0; i < 4; i++)
        #pragma unroll
        for (int j = 0; j < 4; j++)
            #pragma unroll
            for (int k = 0; k < 4; k++) acc[i][j][k] = 0.f;

    {
        CP_ASYNC16(sb + dA0,        Ag + (size_t)lr0 * DMODEL + lc * 8);
        CP_ASYNC16(sb + dA1,        Ag + (size_t)lr1 * DMODEL + lc * 8);
        CP_ASYNC16(sb + 8192 + dA0, Bg + (size_t)lr0 * DMODEL + lc * 8);
        CP_ASYNC16(sb + 8192 + dA1, Bg + (size_t)lr1 * DMODEL + lc * 8);
        CP_COMMIT();
    }

    for (int it = 0; it < 24; ++it) {
        if (it + 1 < 24) {
            uint32_t stg = sb + ((it + 1) & 1) * 16384;
            int k0 = (it + 1) * 32;
            CP_ASYNC16(stg + dA0,        Ag + (size_t)lr0 * DMODEL + k0 + lc * 8);
            CP_ASYNC16(stg + dA1,        Ag + (size_t)lr1 * DMODEL + k0 + lc * 8);
            CP_ASYNC16(stg + 8192 + dA0, Bg + (size_t)lr0 * DMODEL + k0 + lc * 8);
            CP_ASYNC16(stg + 8192 + dA1, Bg + (size_t)lr1 * DMODEL + k0 + lc * 8);
            CP_COMMIT();
            CP_WAIT(1);
        } else {
            CP_WAIT(0);
        }
        __syncthreads();

        uint32_t aB = sb + (it & 1) * 16384;
        uint32_t bB = aB + 8192;
        #pragma unroll
        for (int ks = 0; ks < 2; ks++) {
            uint32_t ar[4][4], br[2][4];
            #pragma unroll
            for (int mi = 0; mi < 4; mi++) {
                int row = wm + mi * 16 + (lane & 15);
                int c = ks * 2 + (lane >> 4);
                LDSM4(ar[mi], aB + sw_off(row, c));
            }
            #pragma unroll
            for (int nb = 0; nb < 2; nb++) {
                int row = wn + nb * 16 + (lane & 7) + ((lane & 16) >> 1);
                int c = ks * 2 + ((lane & 8) >> 3);
                LDSM4(br[nb], bB + sw_off(row, c));
            }
            #pragma unroll
            for (int mi = 0; mi < 4; mi++)
                #pragma unroll
                for (int ni = 0; ni < 4; ni++)
                    mma16816(acc[mi][ni], ar[mi],
                             br[ni >> 1][(ni & 1) * 2], br[ni >> 1][(ni & 1) * 2 + 1]);
        }
        __syncthreads();
    }

    // epilogue: c0,c1 -> (row, col..col+1); c2,c3 -> (row+8, ..)
    #pragma unroll
    for (int mi = 0; mi < 4; mi++) {
        int row = m0 + wm + mi * 16 + (lane >> 2);
        #pragma unroll
        for (int ni = 0; ni < 4; ni++) {
            int col = n0 + wn + ni * 8 + (lane & 3) * 2;
            float b0 = (col < Nreal) ? bias[col] : 0.f;
            float b1 = (col + 1 < Nreal) ? bias[col + 1] : 0.f;
            if (MODE == 0) {
                float* C = (float*)Cv;
                float2 v0 = { acc[mi][ni][0] + b0, acc[mi][ni][1] + b1 };
                float2 v1 = { acc[mi][ni][2] + b0, acc[mi][ni][3] + b1 };
                *(float2*)(C + (size_t)row * ldc + col) = v0;
                *(float2*)(C + (size_t)(row + 8) * ldc + col) = v1;
            } else if (MODE == 1) {
                __nv_bfloat16* C = (__nv_bfloat16*)Cv;
                __nv_bfloat162 v0 = __floats2bfloat162_rn(acc[mi][ni][0] + b0,
                                                          acc[mi][ni][1] + b1);
                __nv_bfloat162 v1 = __floats2bfloat162_rn(acc[mi][ni][2] + b0,
                                                          acc[mi][ni][3] + b1);
                *(__nv_bfloat162*)(C + (size_t)row * ldc + col) = v0;
                *(__nv_bfloat162*)(C + (size_t)(row + 8) * ldc + col) = v1;
            } else {
                float* C = (float*)Cv;
                float g0 = gamma[col], g1 = gamma[col + 1];
                int r0 = row, r1 = row + 8;
                int d0 = ((r0 >> 10) << 10) + dest[r0];
                int d1 = ((r1 >> 10) << 10) + dest[r1];
                float2 q0 = *(const float2*)(query + (size_t)r0 * DMODEL + col);
                float2 q1 = *(const float2*)(query + (size_t)r1 * DMODEL + col);
                float2 v0 = { q0.x + g0 * (acc[mi][ni][0] + b0),
                              q0.y + g1 * (acc[mi][ni][1] + b1) };
                float2 v1 = { q1.x + g0 * (acc[mi][ni][2] + b0),
                              q1.y + g1 * (acc[mi][ni][3] + b1) };
                *(float2*)(C + (size_t)d0 * DMODEL + col) = v0;
                *(float2*)(C + (size_t)d1 * DMODEL + col) = v1;
            }
        }
    }
}

// -------------------- weight transpose+pad: Wt[n][k] = W[k][n] (bf16) ------
__global__ void transpose_pad(const float* __restrict__ W, __nv_bfloat16* __restrict__ Wt,
                              int N, int Npad) {
    int k = blockIdx.x * 256 + threadIdx.x;
    int n = blockIdx.y;
    float v = (n < N) ? W[(size_t)k * N + n] : 0.f;
    Wt[(size_t)n * DMODEL + k] = __float2bfloat16(v);
}

// -------------------- LayerNorm (f32 in -> bf16 out) -----------------------
__global__ void ln_kernel(const float* __restrict__ x,
                          const float* __restrict__ sc,
                          const float* __restrict__ bi,
                          __nv_bfloat16* __restrict__ y) {
    int row = blockIdx.x;
    int t = threadIdx.x;
    const float* xr = x + (size_t)row * DMODEL;
    float v0 = xr[t], v1 = xr[t + 256], v2 = xr[t + 512];
    float sum = v0 + v1 + v2;
    float sq  = v0 * v0 + v1 * v1 + v2 * v2;
    #pragma unroll
    for (int o = 16; o > 0; o >>= 1) {
        sum += __shfl_xor_sync(0xffffffffu, sum, o);
        sq  += __shfl_xor_sync(0xffffffffu, sq,  o);
    }
    __shared__ float ssum[8], ssq[8];
    __shared__ float smean, sinv;
    if ((t & 31) == 0) { ssum[t >> 5] = sum; ssq[t >> 5] = sq; }
    __syncthreads();
    if (t == 0) {
        float S = 0.f, Q = 0.f;
        #pragma unroll
        for (int w = 0; w < 8; w++) { S += ssum[w]; Q += ssq[w]; }
        float mean = S * (1.0f / DMODEL);
        float var  = Q * (1.0f / DMODEL) - mean * mean;
        smean = mean;
        sinv  = rsqrtf(var + 1e-6f);
    }
    __syncthreads();
    float mean = smean, inv = sinv;
    __nv_bfloat16* yr = y + (size_t)row * DMODEL;
    yr[t]       = __float2bfloat16((v0 - mean) * inv * sc[t]       + bi[t]);
    yr[t + 256] = __float2bfloat16((v1 - mean) * inv * sc[t + 256] + bi[t + 256]);
    yr[t + 512] = __float2bfloat16((v2 - mean) * inv * sc[t + 512] + bi[t + 512]);
}

// -------------------- MSDeformAttn sampling (bf16 value) -------------------
__global__ __launch_bounds__(128) void msda_sample_kernel(
    const float* __restrict__ off,
    const float* __restrict__ logits,
    const __nv_bfloat16* __restrict__ value,
    __nv_bfloat16* __restrict__ out) {
    __shared__ float sl[72];
    __shared__ float saw[72];
    __shared__ int   srow[72][4];
    __shared__ float swgt[72][4];

    int row = blockIdx.x;
    int b = row >> 10, q = row & 1023;
    int t = threadIdx.x;

    if (t < 72) sl[t] = logits[(size_t)row * ATT_LD + t];
    __syncthreads();

    if (t < 6) {
        float mx = -1e30f;
        #pragma unroll
        for (int s = 0; s < 12; s++) mx = fmaxf(mx, sl[t * 12 + s]);
        float e[12], sum = 0.f;
        #pragma unroll
        for (int s = 0; s < 12; s++) { e[s] = expf(sl[t * 12 + s] - mx); sum += e[s]; }
        float inv = 1.f / sum;
        #pragma unroll
        for (int s = 0; s < 12; s++) saw[t * 12 + s] = e[s] * inv;
    }
    __syncthreads();

    if (t < 72) {
        int h = t / 12, s = t % 12, lvl = s >> 2, p = s & 3;
        const int DIMS[3] = {64, 32, 16};
        const int ST[3]   = {0, 4096, 5120};
        int Hd = DIMS[lvl], Wd = DIMS[lvl], st = ST[lvl];
        float refx = ((q & 31) + 0.5f) * (1.0f / 32.0f);
        float refy = ((q >> 5) + 0.5f) * (1.0f / 32.0f);
        size_t obase = (size_t)row * OFF_LD + h * 24 + lvl * 8 + p * 2;
        float ox = off[obase + 0];
        float oy = off[obase + 1];
        float x = (refx + ox / (float)Wd) * (float)Wd - 0.5f;
        float y = (refy + oy / (float)Hd) * (float)Hd - 0.5f;
        float x0 = floorf(x), y0 = floorf(y);
        float wx1 = x - x0, wy1 = y - y0;
        int x0i = (int)x0, y0i = (int)y0;
        float aw = saw[t];
        #pragma unroll
        for (int c = 0; c < 4; c++) {
            int dx = c & 1, dy = c >> 1;
            int xi = x0i + dx, yi = y0i + dy;
            bool valid = (xi >= 0) && (xi < Wd) && (yi >= 0) && (yi < Hd);
            float wx = dx ? wx1 : 1.f - wx1;
            float wy = dy ? wy1 : 1.f - wy1;
            srow[t][c] = valid ? (st + yi * Wd + xi) : -1;
            swgt[t][c] = aw * wx * wy;
        }
    }
    __syncthreads();

    int d = t;
    const __nv_bfloat16* vb = value + (size_t)b * LIN * DMODEL + d;
    __nv_bfloat16* orow = out + (size_t)row * DMODEL + d;
    #pragma unroll 1
    for (int h = 0; h < NHEAD; h++) {
        float acc = 0.f;
        const __nv_bfloat16* vh = vb + h * DHEAD;
        #pragma unroll 1
        for (int s = 0; s < 12; s++) {
            int tt = h * 12 + s;
            #pragma unroll
            for (int c = 0; c < 4; c++) {
                int r = srow[tt][c];
                if (r >= 0) acc += swgt[tt][c] * __bfloat162float(vh[(size_t)r * DMODEL]);
            }
        }
        orow[h * DHEAD] = __float2bfloat16(acc);
    }
}

// -------------------- stable mask-descending destinations ------------------
__global__ void dest_kernel(const void* __restrict__ mraw, int* __restrict__ dest) {
    __shared__ int flagA, flagB;
    __shared__ int s[1024];
    int b = blockIdx.x, i = threadIdx.x;
    const unsigned char* mb = (const unsigned char*)mraw;
    if (i == 0) { flagA = 0; flagB = 0; }
    __syncthreads();
    int la = 0, lb = 0;
    for (int j = i; j < 8192; j += 1024) {
        if (mb[j]) { if ((j & 3) == 0) la = 1; else lb = 1; }
    }
    if (la) atomicOr(&flagA, 1);
    if (lb) atomicOr(&flagB, 1);
    __syncthreads();
    int a = flagA, bb = flagB;
    int idx = (b << 10) + i;
    int m;
    if (a && !bb)        m = (((const int*)mraw)[idx] != 0);
    else if (!a && bb)   m = (((const float*)mraw)[idx] != 0.0f);
    else                 m = (mb[idx] != 0);
    s[i] = m;
    __syncthreads();
    for (int off = 1; off < 1024; off <<= 1) {
        int v = (i >= off) ? s[i - off] : 0;
        __syncthreads();
        s[i] += v;
        __syncthreads();
    }
    int incl = s[i];
    int T = s[1023];
    int excl = incl - m;
    dest[idx] = m ? excl : (T + i - excl);
}

// -------------------- launch -----------------------------------------------
extern "C" void kernel_launch(void* const* d_in, const int* in_sizes, int n_in,
                              void* d_out, int out_size) {
    const float* query  = (const float*)d_in[0];
    const float* feat   = (const float*)d_in[1];
    const void*  mask   = d_in[2];
    const float* ln_q_s = (const float*)d_in[3];
    const float* ln_q_b = (const float*)d_in[4];
    const float* ln_f_s = (const float*)d_in[5];
    const float* ln_f_b = (const float*)d_in[6];
    const float* W_val  = (const float*)d_in[7];
    const float* b_val  = (const float*)d_in[8];
    const float* W_off  = (const float*)d_in[9];
    const float* b_off  = (const float*)d_in[10];
    const float* W_attn = (const float*)d_in[11];
    const float* b_attn = (const float*)d_in[12];
    const float* W_out  = (const float*)d_in[13];
    const float* b_out  = (const float*)d_in[14];
    const float* gamma  = (const float*)d_in[15];
    float* out = (float*)d_out;

    __nv_bfloat16 *qbf, *fbf, *valb, *sampb, *wvalT, *woutT, *woffT, *wattnT;
    float *off_s, *al_s;
    int* dest_s;
    cudaGetSymbolAddress((void**)&qbf,    g_qbf);
    cudaGetSymbolAddress((void**)&fbf,    g_fbf);
    cudaGetSymbolAddress((void**)&valb,   g_valueb);
    cudaGetSymbolAddress((void**)&off_s,  g_off);
    cudaGetSymbolAddress((void**)&al_s,   g_attnlog);
    cudaGetSymbolAddress((void**)&sampb,  g_sampb);
    cudaGetSymbolAddress((void**)&dest_s, g_dest);
    cudaGetSymbolAddress((void**)&wvalT,  g_wvalT);
    cudaGetSymbolAddress((void**)&woutT,  g_woutT);
    cudaGetSymbolAddress((void**)&woffT,  g_woffT);
    cudaGetSymbolAddress((void**)&wattnT, g_wattnT);

    dest_kernel<<<BATCH, 1024>>>(mask, dest_s);

    transpose_pad<<<dim3(3, DMODEL), 256>>>(W_val,  wvalT,  DMODEL,   DMODEL);
    transpose_pad<<<dim3(3, OFF_LD), 256>>>(W_off,  woffT,  OFFCOLS,  OFF_LD);
    transpose_pad<<<dim3(3, ATT_LD), 256>>>(W_attn, wattnT, ATTNCOLS, ATT_LD);
    transpose_pad<<<dim3(3, DMODEL), 256>>>(W_out,  woutT,  DMODEL,   DMODEL);

    ln_kernel<<<NQROWS, 256>>>(query, ln_q_s, ln_q_b, qbf);
    ln_kernel<<<NFROWS, 256>>>(feat,  ln_f_s, ln_f_b, fbf);

    // value = f @ W_val + b_val  (43008 x 768 x 768) -> bf16
    mma_gemm<1><<<dim3(6, NFROWS / 128), 256>>>(fbf, wvalT, b_val, valb,
                                                DMODEL, DMODEL, nullptr, nullptr, nullptr);
    // off = q @ W_off + b_off    (8192 x 144 x 768), ldc=256
    mma_gemm<0><<<dim3(2, NQROWS / 128), 256>>>(qbf, woffT, b_off, off_s,
                                                OFFCOLS, OFF_LD, nullptr, nullptr, nullptr);
    // attn logits = q @ W_attn   (8192 x 72 x 768), ldc=128
    mma_gemm<0><<<dim3(1, NQROWS / 128), 256>>>(qbf, wattnT, b_attn, al_s,
                                                ATTNCOLS, ATT_LD, nullptr, nullptr, nullptr);

    msda_sample_kernel<<<NQROWS, 128>>>(off_s, al_s, valb, sampb);

    // fused: out[dest] = query + gamma * (samp @ W_out + b_out)
    mma_gemm<2><<<dim3(6, NQROWS / 128), 256>>>(sampb, woutT, b_out, out,
                                                DMODEL, DMODEL, query, gamma, dest_s);
}

// round 10
// speedup vs baseline: 1.0656x; 1.0656x over previous
#include <cuda_runtime.h>
#include <cuda_bf16.h>
#include <cstdint>
#include <cstddef>

// ---------------------------------------------------------------------------
// SelectiveViTAdapter: LN(q), LN(f) -> MSDeformAttn -> gamma residual -> stable
// mask-descending sort gather.
// All GEMMs: ldmatrix + mma.sync m16n8k16 bf16 (fp32 acc), cp.async 2-stage.
// off+attn GEMMs merged (N=384 combined); out GEMM fuses residual+scatter.
// NOTE: tcgen05 is NOT compilable in this harness (.target sm_100) — do not use.
// ---------------------------------------------------------------------------

#define BATCH 8
#define DMODEL 768
#define NHEAD 6
#define DHEAD 128
#define LQ 1024
#define LIN 5376
#define NQROWS (BATCH * LQ)      // 8192
#define NFROWS (BATCH * LIN)     // 43008
#define OA_LD 384                // combined off(256) + attn(128) padded cols

// -------------------- scratch (static device globals) ----------------------
__device__ __nv_bfloat16 g_qbf[NQROWS * DMODEL];
__device__ __nv_bfloat16 g_fbf[NFROWS * DMODEL];
__device__ __nv_bfloat16 g_valueb[NFROWS * DMODEL];
__device__ float         g_oa[NQROWS * OA_LD];       // off cols [0,144); logits cols [256,328)
__device__ __nv_bfloat16 g_sampb[NQROWS * DMODEL];
__device__ int           g_dest[NQROWS];
__device__ __nv_bfloat16 g_wvalT[DMODEL * DMODEL];
__device__ __nv_bfloat16 g_woutT[DMODEL * DMODEL];
__device__ __nv_bfloat16 g_woaT[OA_LD * DMODEL];
__device__ float         g_boa[OA_LD];

// -------------------- PTX helpers ------------------------------------------
__device__ __forceinline__ uint32_t smem_u32(const void* p) {
    uint32_t a;
    asm("{ .reg .u64 t; cvta.to.shared.u64 t, %1; cvt.u32.u64 %0, t; }" : "=r"(a) : "l"(p));
    return a;
}
#define CP_ASYNC16(dst, src) asm volatile("cp.async.cg.shared.global [%0], [%1], 16;" :: "r"(dst), "l"(src) : "memory")
#define CP_COMMIT()          asm volatile("cp.async.commit_group;" ::: "memory")
#define CP_WAIT(n)           asm volatile("cp.async.wait_group %0;" :: "n"(n) : "memory")
#define LDSM4(r, a) asm volatile("ldmatrix.sync.aligned.m8n8.x4.shared.b16 {%0,%1,%2,%3}, [%4];" \
    : "=r"((r)[0]), "=r"((r)[1]), "=r"((r)[2]), "=r"((r)[3]) : "r"(a))

__device__ __forceinline__ void mma16816(float* c, const uint32_t* a, uint32_t b0, uint32_t b1) {
    asm volatile(
        "mma.sync.aligned.m16n8k16.row.col.f32.bf16.bf16.f32 "
        "{%0,%1,%2,%3}, {%4,%5,%6,%7}, {%8,%9}, {%0,%1,%2,%3};"
        : "+f"(c[0]), "+f"(c[1]), "+f"(c[2]), "+f"(c[3])
        : "r"(a[0]), "r"(a[1]), "r"(a[2]), "r"(a[3]), "r"(b0), "r"(b1));
}
// Swizzled smem offset for [rows x 32 bf16] tiles (64B rows, 16B chunks).
__device__ __forceinline__ uint32_t sw_off(int r, int c) {
    return (uint32_t)(r * 64 + ((c ^ ((r >> 1) & 3)) << 4));
}

// -------------------- bf16 tensor-core GEMM --------------------------------
// MODE 0: C f32 = A@Bt^T + bias (padded bias array, ldc stride)
// MODE 1: C bf16 = A@Bt^T + bias (value GEMM)
// MODE 2: out[dest-row] f32 = query[row] + gamma*(acc + bias)
template <int MODE>
__global__ __launch_bounds__(256) void mma_gemm(
    const __nv_bfloat16* __restrict__ A, const __nv_bfloat16* __restrict__ Bt,
    const float* __restrict__ bias, void* __restrict__ Cv,
    int ldc,
    const float* __restrict__ query, const float* __restrict__ gamma,
    const int* __restrict__ dest) {
    __shared__ __align__(128) char smbuf[2 * 16384];
    uint32_t sb = smem_u32(smbuf);
    int tid = threadIdx.x, wid = tid >> 5, lane = tid & 31;
    int m0 = blockIdx.y * 128, n0 = blockIdx.x * 128;
    int wm = (wid >> 2) * 64, wn = (wid & 3) * 32;

    const __nv_bfloat16* Ag = A + (size_t)m0 * DMODEL;
    const __nv_bfloat16* Bg = Bt + (size_t)n0 * DMODEL;

    int lr0 = tid >> 2, lc = tid & 3;
    int lr1 = lr0 + 64;
    uint32_t dA0 = sw_off(lr0, lc), dA1 = sw_off(lr1, lc);

    float acc[4][4][4];
    #pragma unroll
    for (int i = 0; i < 4; i++)
        #pragma unroll
        for (int j = 0; j < 4; j++)
            #pragma unroll
            for (int k = 0; k < 4; k++) acc[i][j][k] = 0.f;

    {
        CP_ASYNC16(sb + dA0,        Ag + (size_t)lr0 * DMODEL + lc * 8);
        CP_ASYNC16(sb + dA1,        Ag + (size_t)lr1 * DMODEL + lc * 8);
        CP_ASYNC16(sb + 8192 + dA0, Bg + (size_t)lr0 * DMODEL + lc * 8);
        CP_ASYNC16(sb + 8192 + dA1, Bg + (size_t)lr1 * DMODEL + lc * 8);
        CP_COMMIT();
    }

    for (int it = 0; it < 24; ++it) {
        if (it + 1 < 24) {
            uint32_t stg = sb + ((it + 1) & 1) * 16384;
            int k0 = (it + 1) * 32;
            CP_ASYNC16(stg + dA0,        Ag + (size_t)lr0 * DMODEL + k0 + lc * 8);
            CP_ASYNC16(stg + dA1,        Ag + (size_t)lr1 * DMODEL + k0 + lc * 8);
            CP_ASYNC16(stg + 8192 + dA0, Bg + (size_t)lr0 * DMODEL + k0 + lc * 8);
            CP_ASYNC16(stg + 8192 + dA1, Bg + (size_t)lr1 * DMODEL + k0 + lc * 8);
            CP_COMMIT();
            CP_WAIT(1);
        } else {
            CP_WAIT(0);
        }
        __syncthreads();

        uint32_t aB = sb + (it & 1) * 16384;
        uint32_t bB = aB + 8192;
        #pragma unroll
        for (int ks = 0; ks < 2; ks++) {
            uint32_t ar[4][4], br[2][4];
            #pragma unroll
            for (int mi = 0; mi < 4; mi++) {
                int row = wm + mi * 16 + (lane & 15);
                int c = ks * 2 + (lane >> 4);
                LDSM4(ar[mi], aB + sw_off(row, c));
            }
            #pragma unroll
            for (int nb = 0; nb < 2; nb++) {
                int row = wn + nb * 16 + (lane & 7) + ((lane & 16) >> 1);
                int c = ks * 2 + ((lane & 8) >> 3);
                LDSM4(br[nb], bB + sw_off(row, c));
            }
            #pragma unroll
            for (int mi = 0; mi < 4; mi++)
                #pragma unroll
                for (int ni = 0; ni < 4; ni++)
                    mma16816(acc[mi][ni], ar[mi],
                             br[ni >> 1][(ni & 1) * 2], br[ni >> 1][(ni & 1) * 2 + 1]);
        }
        __syncthreads();
    }

    // epilogue: c0,c1 -> (row, col..col+1); c2,c3 -> (row+8, ..)
    #pragma unroll
    for (int mi = 0; mi < 4; mi++) {
        int row = m0 + wm + mi * 16 + (lane >> 2);
        #pragma unroll
        for (int ni = 0; ni < 4; ni++) {
            int col = n0 + wn + ni * 8 + (lane & 3) * 2;
            float b0 = bias[col];
            float b1 = bias[col + 1];
            if (MODE == 0) {
                float* C = (float*)Cv;
                float2 v0 = { acc[mi][ni][0] + b0, acc[mi][ni][1] + b1 };
                float2 v1 = { acc[mi][ni][2] + b0, acc[mi][ni][3] + b1 };
                *(float2*)(C + (size_t)row * ldc + col) = v0;
                *(float2*)(C + (size_t)(row + 8) * ldc + col) = v1;
            } else if (MODE == 1) {
                __nv_bfloat16* C = (__nv_bfloat16*)Cv;
                __nv_bfloat162 v0 = __floats2bfloat162_rn(acc[mi][ni][0] + b0,
                                                          acc[mi][ni][1] + b1);
                __nv_bfloat162 v1 = __floats2bfloat162_rn(acc[mi][ni][2] + b0,
                                                          acc[mi][ni][3] + b1);
                *(__nv_bfloat162*)(C + (size_t)row * ldc + col) = v0;
                *(__nv_bfloat162*)(C + (size_t)(row + 8) * ldc + col) = v1;
            } else {
                float* C = (float*)Cv;
                float g0 = gamma[col], g1 = gamma[col + 1];
                int r0 = row, r1 = row + 8;
                int d0 = ((r0 >> 10) << 10) + dest[r0];
                int d1 = ((r1 >> 10) << 10) + dest[r1];
                float2 q0 = *(const float2*)(query + (size_t)r0 * DMODEL + col);
                float2 q1 = *(const float2*)(query + (size_t)r1 * DMODEL + col);
                float2 v0 = { q0.x + g0 * (acc[mi][ni][0] + b0),
                              q0.y + g1 * (acc[mi][ni][1] + b1) };
                float2 v1 = { q1.x + g0 * (acc[mi][ni][2] + b0),
                              q1.y + g1 * (acc[mi][ni][3] + b1) };
                *(float2*)(C + (size_t)d0 * DMODEL + col) = v0;
                *(float2*)(C + (size_t)d1 * DMODEL + col) = v1;
            }
        }
    }
}

// -------------------- fused weight prep ------------------------------------
// One launch builds wvalT, woutT, combined off+attn weight (padded) + bias.
// grid = (3, 1920); rows: [0,768) val, [768,1536) out, [1536,1792) off(pad 256),
// [1792,1920) attn(pad 128).
__global__ void prep_weights(const float* __restrict__ Wv, const float* __restrict__ Wo,
                             const float* __restrict__ Wf, const float* __restrict__ Wa,
                             const float* __restrict__ boff, const float* __restrict__ batt,
                             __nv_bfloat16* __restrict__ wvalT,
                             __nv_bfloat16* __restrict__ woutT,
                             __nv_bfloat16* __restrict__ woaT,
                             float* __restrict__ boa) {
    int k = blockIdx.x * 256 + threadIdx.x;   // 0..767
    int r = blockIdx.y;
    if (r < 768) {
        wvalT[(size_t)r * DMODEL + k] = __float2bfloat16(Wv[(size_t)k * DMODEL + r]);
    } else if (r < 1536) {
        int n = r - 768;
        woutT[(size_t)n * DMODEL + k] = __float2bfloat16(Wo[(size_t)k * DMODEL + n]);
    } else if (r < 1792) {
        int n = r - 1536;
        float v = (n < 144) ? Wf[(size_t)k * 144 + n] : 0.f;
        woaT[(size_t)n * DMODEL + k] = __float2bfloat16(v);
    } else {
        int n = r - 1792;
        float v = (n < 72) ? Wa[(size_t)k * 72 + n] : 0.f;
        woaT[(size_t)(256 + n) * DMODEL + k] = __float2bfloat16(v);
    }
    if (blockIdx.y == 0 && blockIdx.x == 0) {
        int t = threadIdx.x;
        boa[t] = (t < 144) ? boff[t] : 0.f;
        if (t < 128) boa[256 + t] = (t < 72) ? batt[t] : 0.f;
    }
}

// -------------------- LayerNorm (f32 in -> bf16 out) -----------------------
__global__ void ln_kernel(const float* __restrict__ x,
                          const float* __restrict__ sc,
                          const float* __restrict__ bi,
                          __nv_bfloat16* __restrict__ y) {
    int row = blockIdx.x;
    int t = threadIdx.x;
    const float* xr = x + (size_t)row * DMODEL;
    float v0 = xr[t], v1 = xr[t + 256], v2 = xr[t + 512];
    float sum = v0 + v1 + v2;
    float sq  = v0 * v0 + v1 * v1 + v2 * v2;
    #pragma unroll
    for (int o = 16; o > 0; o >>= 1) {
        sum += __shfl_xor_sync(0xffffffffu, sum, o);
        sq  += __shfl_xor_sync(0xffffffffu, sq,  o);
    }
    __shared__ float ssum[8], ssq[8];
    __shared__ float smean, sinv;
    if ((t & 31) == 0) { ssum[t >> 5] = sum; ssq[t >> 5] = sq; }
    __syncthreads();
    if (t == 0) {
        float S = 0.f, Q = 0.f;
        #pragma unroll
        for (int w = 0; w < 8; w++) { S += ssum[w]; Q += ssq[w]; }
        float mean = S * (1.0f / DMODEL);
        float var  = Q * (1.0f / DMODEL) - mean * mean;
        smean = mean;
        sinv  = rsqrtf(var + 1e-6f);
    }
    __syncthreads();
    float mean = smean, inv = sinv;
    __nv_bfloat16* yr = y + (size_t)row * DMODEL;
    yr[t]       = __float2bfloat16((v0 - mean) * inv * sc[t]       + bi[t]);
    yr[t + 256] = __float2bfloat16((v1 - mean) * inv * sc[t + 256] + bi[t + 256]);
    yr[t + 512] = __float2bfloat16((v2 - mean) * inv * sc[t + 512] + bi[t + 512]);
}

// -------------------- MSDeformAttn sampling (bf16 value) -------------------
// oa layout per row (stride OA_LD): off at cols [0,144), logits at [256,328).
__global__ __launch_bounds__(128) void msda_sample_kernel(
    const float* __restrict__ oa,
    const __nv_bfloat16* __restrict__ value,
    __nv_bfloat16* __restrict__ out) {
    __shared__ float sl[72];
    __shared__ float saw[72];
    __shared__ int   srow[72][4];
    __shared__ float swgt[72][4];

    int row = blockIdx.x;
    int b = row >> 10, q = row & 1023;
    int t = threadIdx.x;

    if (t < 72) sl[t] = oa[(size_t)row * OA_LD + 256 + t];
    __syncthreads();

    if (t < 6) {
        float mx = -1e30f;
        #pragma unroll
        for (int s = 0; s < 12; s++) mx = fmaxf(mx, sl[t * 12 + s]);
        float e[12], sum = 0.f;
        #pragma unroll
        for (int s = 0; s < 12; s++) { e[s] = expf(sl[t * 12 + s] - mx); sum += e[s]; }
        float inv = 1.f / sum;
        #pragma unroll
        for (int s = 0; s < 12; s++) saw[t * 12 + s] = e[s] * inv;
    }
    __syncthreads();

    if (t < 72) {
        int h = t / 12, s = t % 12, lvl = s >> 2, p = s & 3;
        const int DIMS[3] = {64, 32, 16};
        const int ST[3]   = {0, 4096, 5120};
        int Hd = DIMS[lvl], Wd = DIMS[lvl], st = ST[lvl];
        float refx = ((q & 31) + 0.5f) * (1.0f / 32.0f);
        float refy = ((q >> 5) + 0.5f) * (1.0f / 32.0f);
        size_t obase = (size_t)row * OA_LD + h * 24 + lvl * 8 + p * 2;
        float ox = oa[obase + 0];
        float oy = oa[obase + 1];
        float x = (refx + ox / (float)Wd) * (float)Wd - 0.5f;
        float y = (refy + oy / (float)Hd) * (float)Hd - 0.5f;
        float x0 = floorf(x), y0 = floorf(y);
        float wx1 = x - x0, wy1 = y - y0;
        int x0i = (int)x0, y0i = (int)y0;
        float aw = saw[t];
        #pragma unroll
        for (int c = 0; c < 4; c++) {
            int dx = c & 1, dy = c >> 1;
            int xi = x0i + dx, yi = y0i + dy;
            bool valid = (xi >= 0) && (xi < Wd) && (yi >= 0) && (yi < Hd);
            float wx = dx ? wx1 : 1.f - wx1;
            float wy = dy ? wy1 : 1.f - wy1;
            srow[t][c] = valid ? (st + yi * Wd + xi) : -1;
            swgt[t][c] = aw * wx * wy;
        }
    }
    __syncthreads();

    int d = t;
    const __nv_bfloat16* vb = value + (size_t)b * LIN * DMODEL + d;
    __nv_bfloat16* orow = out + (size_t)row * DMODEL + d;
    #pragma unroll 1
    for (int h = 0; h < NHEAD; h++) {
        float acc = 0.f;
        const __nv_bfloat16* vh = vb + h * DHEAD;
        #pragma unroll 1
        for (int s = 0; s < 12; s++) {
            int tt = h * 12 + s;
            #pragma unroll
            for (int c = 0; c < 4; c++) {
                int r = srow[tt][c];
                if (r >= 0) acc += swgt[tt][c] * __bfloat162float(vh[(size_t)r * DMODEL]);
            }
        }
        orow[h * DHEAD] = __float2bfloat16(acc);
    }
}

// -------------------- stable mask-descending destinations ------------------
__global__ void dest_kernel(const void* __restrict__ mraw, int* __restrict__ dest) {
    __shared__ int flagA, flagB;
    __shared__ int s[1024];
    int b = blockIdx.x, i = threadIdx.x;
    const unsigned char* mb = (const unsigned char*)mraw;
    if (i == 0) { flagA = 0; flagB = 0; }
    __syncthreads();
    int la = 0, lb = 0;
    for (int j = i; j < 8192; j += 1024) {
        if (mb[j]) { if ((j & 3) == 0) la = 1; else lb = 1; }
    }
    if (la) atomicOr(&flagA, 1);
    if (lb) atomicOr(&flagB, 1);
    __syncthreads();
    int a = flagA, bb = flagB;
    int idx = (b << 10) + i;
    int m;
    if (a && !bb)        m = (((const int*)mraw)[idx] != 0);
    else if (!a && bb)   m = (((const float*)mraw)[idx] != 0.0f);
    else                 m = (mb[idx] != 0);
    s[i] = m;
    __syncthreads();
    for (int off = 1; off < 1024; off <<= 1) {
        int v = (i >= off) ? s[i - off] : 0;
        __syncthreads();
        s[i] += v;
        __syncthreads();
    }
    int incl = s[i];
    int T = s[1023];
    int excl = incl - m;
    dest[idx] = m ? excl : (T + i - excl);
}

// -------------------- launch -----------------------------------------------
extern "C" void kernel_launch(void* const* d_in, const int* in_sizes, int n_in,
                              void* d_out, int out_size) {
    const float* query  = (const float*)d_in[0];
    const float* feat   = (const float*)d_in[1];
    const void*  mask   = d_in[2];
    const float* ln_q_s = (const float*)d_in[3];
    const float* ln_q_b = (const float*)d_in[4];
    const float* ln_f_s = (const float*)d_in[5];
    const float* ln_f_b = (const float*)d_in[6];
    const float* W_val  = (const float*)d_in[7];
    const float* b_val  = (const float*)d_in[8];
    const float* W_off  = (const float*)d_in[9];
    const float* b_off  = (const float*)d_in[10];
    const float* W_attn = (const float*)d_in[11];
    const float* b_attn = (const float*)d_in[12];
    const float* W_out  = (const float*)d_in[13];
    const float* b_out  = (const float*)d_in[14];
    const float* gamma  = (const float*)d_in[15];
    float* out = (float*)d_out;

    __nv_bfloat16 *qbf, *fbf, *valb, *sampb, *wvalT, *woutT, *woaT;
    float *oa_s, *boa;
    int* dest_s;
    cudaGetSymbolAddress((void**)&qbf,    g_qbf);
    cudaGetSymbolAddress((void**)&fbf,    g_fbf);
    cudaGetSymbolAddress((void**)&valb,   g_valueb);
    cudaGetSymbolAddress((void**)&oa_s,   g_oa);
    cudaGetSymbolAddress((void**)&sampb,  g_sampb);
    cudaGetSymbolAddress((void**)&dest_s, g_dest);
    cudaGetSymbolAddress((void**)&wvalT,  g_wvalT);
    cudaGetSymbolAddress((void**)&woutT,  g_woutT);
    cudaGetSymbolAddress((void**)&woaT,   g_woaT);
    cudaGetSymbolAddress((void**)&boa,    g_boa);

    // 1: fused weight prep
    prep_weights<<<dim3(3, 1920), 256>>>(W_val, W_out, W_off, W_attn,
                                         b_off, b_attn, wvalT, woutT, woaT, boa);
    // 2-3: LayerNorms
    ln_kernel<<<NQROWS, 256>>>(query, ln_q_s, ln_q_b, qbf);
    ln_kernel<<<NFROWS, 256>>>(feat,  ln_f_s, ln_f_b, fbf);
    // 4: destinations
    dest_kernel<<<BATCH, 1024>>>(mask, dest_s);
    // 5: combined off+attn GEMM (8192 x 384 x 768)
    mma_gemm<0><<<dim3(3, NQROWS / 128), 256>>>(qbf, woaT, boa, oa_s,
                                                OA_LD, nullptr, nullptr, nullptr);
    // 6: value GEMM (43008 x 768 x 768) -> bf16   [ncu -s 5 captures this]
    mma_gemm<1><<<dim3(6, NFROWS / 128), 256>>>(fbf, wvalT, b_val, valb,
                                                DMODEL, nullptr, nullptr, nullptr);
    // 7: sampling
    msda_sample_kernel<<<NQROWS, 128>>>(oa_s, valb, sampb);
    // 8: fused out GEMM: out[dest] = query + gamma*(samp @ W_out + b_out)
    mma_gemm<2><<<dim3(6, NQROWS / 128), 256>>>(sampb, woutT, b_out, out,
                                                DMODEL, query, gamma, dest_s);
}

// round 12
// speedup vs baseline: 1.1260x; 1.0567x over previous
#include <cuda_runtime.h>
#include <cuda_bf16.h>
#include <cstdint>
#include <cstddef>

// ---------------------------------------------------------------------------
// SelectiveViTAdapter: LN(q), LN(f) -> MSDeformAttn -> gamma residual -> stable
// mask-descending sort gather.
// 4 launches: misc(LNq+LNf+dest+prep) -> bigGEMM(value+oa) -> sampler ->
// outGEMM(fused residual+scatter).  mma.sync bf16 only (tcgen05 not compilable
// here; streams/events break harness graph capture — both verified).
// ---------------------------------------------------------------------------

#define BATCH 8
#define DMODEL 768
#define NHEAD 6
#define DHEAD 128
#define LQ 1024
#define LIN 5376
#define NQROWS (BATCH * LQ)      // 8192
#define NFROWS (BATCH * LIN)     // 43008
#define OA_LD 384                // combined off(256) + attn(128) padded cols

// -------------------- scratch (static device globals) ----------------------
__device__ __nv_bfloat16 g_qbf[NQROWS * DMODEL];
__device__ __nv_bfloat16 g_fbf[NFROWS * DMODEL];
__device__ __nv_bfloat16 g_valueb[NFROWS * DMODEL];
__device__ float         g_oa[NQROWS * OA_LD];       // off cols [0,144); logits [256,328)
__device__ __nv_bfloat16 g_sampb[NQROWS * DMODEL];
__device__ int           g_dest[NQROWS];
__device__ __nv_bfloat16 g_wvalT[DMODEL * DMODEL];
__device__ __nv_bfloat16 g_woutT[DMODEL * DMODEL];
__device__ __nv_bfloat16 g_woaT[OA_LD * DMODEL];
__device__ float         g_boa[OA_LD];

// -------------------- PTX helpers ------------------------------------------
__device__ __forceinline__ uint32_t smem_u32(const void* p) {
    uint32_t a;
    asm("{ .reg .u64 t; cvta.to.shared.u64 t, %1; cvt.u32.u64 %0, t; }" : "=r"(a) : "l"(p));
    return a;
}
#define CP_ASYNC16(dst, src) asm volatile("cp.async.cg.shared.global [%0], [%1], 16;" :: "r"(dst), "l"(src) : "memory")
#define CP_COMMIT()          asm volatile("cp.async.commit_group;" ::: "memory")
#define CP_WAIT(n)           asm volatile("cp.async.wait_group %0;" :: "n"(n) : "memory")
#define LDSM4(r, a) asm volatile("ldmatrix.sync.aligned.m8n8.x4.shared.b16 {%0,%1,%2,%3}, [%4];" \
    : "=r"((r)[0]), "=r"((r)[1]), "=r"((r)[2]), "=r"((r)[3]) : "r"(a))

__device__ __forceinline__ void mma16816(float* c, const uint32_t* a, uint32_t b0, uint32_t b1) {
    asm volatile(
        "mma.sync.aligned.m16n8k16.row.col.f32.bf16.bf16.f32 "
        "{%0,%1,%2,%3}, {%4,%5,%6,%7}, {%8,%9}, {%0,%1,%2,%3};"
        : "+f"(c[0]), "+f"(c[1]), "+f"(c[2]), "+f"(c[3])
        : "r"(a[0]), "r"(a[1]), "r"(a[2]), "r"(a[3]), "r"(b0), "r"(b1));
}
// Swizzled smem offset for [rows x 32 bf16] tiles (64B rows, 16B chunks).
__device__ __forceinline__ uint32_t sw_off(int r, int c) {
    return (uint32_t)(r * 64 + ((c ^ ((r >> 1) & 3)) << 4));
}

// -------------------- shared GEMM mainloop ---------------------------------
// acc[4][4][4] += A[128 x 768] @ B[128 x 768]^T tile product.
// smbuf: 32KB double-buffered staging. 256 threads, 8 warps (2x4), 64x32 warp tile.
__device__ __forceinline__ void gemm_mainloop(
    const __nv_bfloat16* __restrict__ Ag, const __nv_bfloat16* __restrict__ Bg,
    char* smbuf, float acc[4][4][4]) {
    uint32_t sb = smem_u32(smbuf);
    int tid = threadIdx.x, wid = tid >> 5, lane = tid & 31;
    int wm = (wid >> 2) * 64, wn = (wid & 3) * 32;
    int lr0 = tid >> 2, lc = tid & 3;
    int lr1 = lr0 + 64;
    uint32_t dA0 = sw_off(lr0, lc), dA1 = sw_off(lr1, lc);

    {
        CP_ASYNC16(sb + dA0,        Ag + (size_t)lr0 * DMODEL + lc * 8);
        CP_ASYNC16(sb + dA1,        Ag + (size_t)lr1 * DMODEL + lc * 8);
        CP_ASYNC16(sb + 8192 + dA0, Bg + (size_t)lr0 * DMODEL + lc * 8);
        CP_ASYNC16(sb + 8192 + dA1, Bg + (size_t)lr1 * DMODEL + lc * 8);
        CP_COMMIT();
    }

    for (int it = 0; it < 24; ++it) {
        if (it + 1 < 24) {
            uint32_t stg = sb + ((it + 1) & 1) * 16384;
            int k0 = (it + 1) * 32;
            CP_ASYNC16(stg + dA0,        Ag + (size_t)lr0 * DMODEL + k0 + lc * 8);
            CP_ASYNC16(stg + dA1,        Ag + (size_t)lr1 * DMODEL + k0 + lc * 8);
            CP_ASYNC16(stg + 8192 + dA0, Bg + (size_t)lr0 * DMODEL + k0 + lc * 8);
            CP_ASYNC16(stg + 8192 + dA1, Bg + (size_t)lr1 * DMODEL + k0 + lc * 8);
            CP_COMMIT();
            CP_WAIT(1);
        } else {
            CP_WAIT(0);
        }
        __syncthreads();

        uint32_t aB = sb + (it & 1) * 16384;
        uint32_t bB = aB + 8192;
        #pragma unroll
        for (int ks = 0; ks < 2; ks++) {
            uint32_t ar[4][4], br[2][4];
            #pragma unroll
            for (int mi = 0; mi < 4; mi++) {
                int row = wm + mi * 16 + (lane & 15);
                int c = ks * 2 + (lane >> 4);
                LDSM4(ar[mi], aB + sw_off(row, c));
            }
            #pragma unroll
            for (int nb = 0; nb < 2; nb++) {
                int row = wn + nb * 16 + (lane & 7) + ((lane & 16) >> 1);
                int c = ks * 2 + ((lane & 8) >> 3);
                LDSM4(br[nb], bB + sw_off(row, c));
            }
            #pragma unroll
            for (int mi = 0; mi < 4; mi++)
                #pragma unroll
                for (int ni = 0; ni < 4; ni++)
                    mma16816(acc[mi][ni], ar[mi],
                             br[ni >> 1][(ni & 1) * 2], br[ni >> 1][(ni & 1) * 2 + 1]);
        }
        __syncthreads();
    }
}

// -------------------- big GEMM: value + oa in one launch --------------------
// blockIdx.y < 336: value tile (C bf16 = fbf @ wvalT^T + b_val, ldc 768)
// blockIdx.y >= 336 && blockIdx.x < 3: oa tile (C f32 = qbf @ woaT^T + boa, ldc 384)
__global__ __launch_bounds__(256) void big_gemm(
    const __nv_bfloat16* __restrict__ Afv, const __nv_bfloat16* __restrict__ Bfv,
    const float* __restrict__ bv, __nv_bfloat16* __restrict__ Cv,
    const __nv_bfloat16* __restrict__ Aoa, const __nv_bfloat16* __restrict__ Boa,
    const float* __restrict__ boa, float* __restrict__ Coa) {
    __shared__ __align__(128) char smbuf[2 * 16384];
    int isOA = (blockIdx.y >= 336);
    if (isOA && blockIdx.x >= 3) return;

    int by = isOA ? (blockIdx.y - 336) : blockIdx.y;
    int m0 = by * 128, n0 = blockIdx.x * 128;
    const __nv_bfloat16* Ag = (isOA ? Aoa : Afv) + (size_t)m0 * DMODEL;
    const __nv_bfloat16* Bg = (isOA ? Boa : Bfv) + (size_t)n0 * DMODEL;

    float acc[4][4][4];
    #pragma unroll
    for (int i = 0; i < 4; i++)
        #pragma unroll
        for (int j = 0; j < 4; j++)
            #pragma unroll
            for (int k = 0; k < 4; k++) acc[i][j][k] = 0.f;

    gemm_mainloop(Ag, Bg, smbuf, acc);

    int wid = threadIdx.x >> 5, lane = threadIdx.x & 31;
    int wm = (wid >> 2) * 64, wn = (wid & 3) * 32;
    const float* bias = isOA ? boa : bv;
    #pragma unroll
    for (int mi = 0; mi < 4; mi++) {
        int row = m0 + wm + mi * 16 + (lane >> 2);
        #pragma unroll
        for (int ni = 0; ni < 4; ni++) {
            int col = n0 + wn + ni * 8 + (lane & 3) * 2;
            float b0 = bias[col], b1 = bias[col + 1];
            if (!isOA) {
                __nv_bfloat162 v0 = __floats2bfloat162_rn(acc[mi][ni][0] + b0,
                                                          acc[mi][ni][1] + b1);
                __nv_bfloat162 v1 = __floats2bfloat162_rn(acc[mi][ni][2] + b0,
                                                          acc[mi][ni][3] + b1);
                *(__nv_bfloat162*)(Cv + (size_t)row * DMODEL + col) = v0;
                *(__nv_bfloat162*)(Cv + (size_t)(row + 8) * DMODEL + col) = v1;
            } else {
                float2 v0 = { acc[mi][ni][0] + b0, acc[mi][ni][1] + b1 };
                float2 v1 = { acc[mi][ni][2] + b0, acc[mi][ni][3] + b1 };
                *(float2*)(Coa + (size_t)row * OA_LD + col) = v0;
                *(float2*)(Coa + (size_t)(row + 8) * OA_LD + col) = v1;
            }
        }
    }
}

// -------------------- out GEMM: fused residual + scatter --------------------
__global__ __launch_bounds__(256) void out_gemm(
    const __nv_bfloat16* __restrict__ A, const __nv_bfloat16* __restrict__ Bt,
    const float* __restrict__ bias, float* __restrict__ C,
    const float* __restrict__ query, const float* __restrict__ gamma,
    const int* __restrict__ dest) {
    __shared__ __align__(128) char smbuf[2 * 16384];
    int m0 = blockIdx.y * 128, n0 = blockIdx.x * 128;
    const __nv_bfloat16* Ag = A + (size_t)m0 * DMODEL;
    const __nv_bfloat16* Bg = Bt + (size_t)n0 * DMODEL;

    float acc[4][4][4];
    #pragma unroll
    for (int i = 0; i < 4; i++)
        #pragma unroll
        for (int j = 0; j < 4; j++)
            #pragma unroll
            for (int k = 0; k < 4; k++) acc[i][j][k] = 0.f;

    gemm_mainloop(Ag, Bg, smbuf, acc);

    int wid = threadIdx.x >> 5, lane = threadIdx.x & 31;
    int wm = (wid >> 2) * 64, wn = (wid & 3) * 32;
    #pragma unroll
    for (int mi = 0; mi < 4; mi++) {
        int row = m0 + wm + mi * 16 + (lane >> 2);
        #pragma unroll
        for (int ni = 0; ni < 4; ni++) {
            int col = n0 + wn + ni * 8 + (lane & 3) * 2;
            float b0 = bias[col], b1 = bias[col + 1];
            float g0 = gamma[col], g1 = gamma[col + 1];
            int r0 = row, r1 = row + 8;
            int d0 = ((r0 >> 10) << 10) + dest[r0];
            int d1 = ((r1 >> 10) << 10) + dest[r1];
            float2 q0 = *(const float2*)(query + (size_t)r0 * DMODEL + col);
            float2 q1 = *(const float2*)(query + (size_t)r1 * DMODEL + col);
            float2 v0 = { q0.x + g0 * (acc[mi][ni][0] + b0),
                          q0.y + g1 * (acc[mi][ni][1] + b1) };
            float2 v1 = { q1.x + g0 * (acc[mi][ni][2] + b0),
                          q1.y + g1 * (acc[mi][ni][3] + b1) };
            *(float2*)(C + (size_t)d0 * DMODEL + col) = v0;
            *(float2*)(C + (size_t)d1 * DMODEL + col) = v1;
        }
    }
}

// -------------------- misc: LN(q) + LN(f) + dest + weight prep -------------
// grid.x partition (256 threads each):
//   [0, 8192)                LN q row
//   [8192, 51200)            LN f row (row-8192)
//   [51200, 53120)           prep row r = bid-51200 over 1920 rows x 3 chunks?
//     -> prep uses (r, kchunk): 1920 rows x 3 k-chunks = 5760 blocks
//   [53120, 53128)           dest batch
// Layout: LNQ_END=8192, LNF_END=51200, PREP_END=56960, DEST_END=56968
#define LNQ_END 8192
#define LNF_END 51200
#define PREP_END 56960
#define DEST_END 56968

__device__ __forceinline__ void ln_row(const float* xr, const float* sc,
                                       const float* bi, __nv_bfloat16* yr) {
    int t = threadIdx.x;
    float v0 = xr[t], v1 = xr[t + 256], v2 = xr[t + 512];
    float sum = v0 + v1 + v2;
    float sq  = v0 * v0 + v1 * v1 + v2 * v2;
    #pragma unroll
    for (int o = 16; o > 0; o >>= 1) {
        sum += __shfl_xor_sync(0xffffffffu, sum, o);
        sq  += __shfl_xor_sync(0xffffffffu, sq,  o);
    }
    __shared__ float ssum[8], ssq[8], smean, sinv;
    if ((t & 31) == 0) { ssum[t >> 5] = sum; ssq[t >> 5] = sq; }
    __syncthreads();
    if (t == 0) {
        float S = 0.f, Q = 0.f;
        #pragma unroll
        for (int w = 0; w < 8; w++) { S += ssum[w]; Q += ssq[w]; }
        float mean = S * (1.0f / DMODEL);
        float var  = Q * (1.0f / DMODEL) - mean * mean;
        smean = mean;
        sinv  = rsqrtf(var + 1e-6f);
    }
    __syncthreads();
    float mean = smean, inv = sinv;
    yr[t]       = __float2bfloat16((v0 - mean) * inv * sc[t]       + bi[t]);
    yr[t + 256] = __float2bfloat16((v1 - mean) * inv * sc[t + 256] + bi[t + 256]);
    yr[t + 512] = __float2bfloat16((v2 - mean) * inv * sc[t + 512] + bi[t + 512]);
}

__global__ __launch_bounds__(256) void misc_kernel(
    const float* __restrict__ query, const float* __restrict__ feat,
    const void* __restrict__ mraw,
    const float* __restrict__ ln_q_s, const float* __restrict__ ln_q_b,
    const float* __restrict__ ln_f_s, const float* __restrict__ ln_f_b,
    const float* __restrict__ Wv, const float* __restrict__ Wo,
    const float* __restrict__ Wf, const float* __restrict__ Wa,
    const float* __restrict__ boff, const float* __restrict__ batt,
    __nv_bfloat16* __restrict__ qbf, __nv_bfloat16* __restrict__ fbf,
    int* __restrict__ dest,
    __nv_bfloat16* __restrict__ wvalT, __nv_bfloat16* __restrict__ woutT,
    __nv_bfloat16* __restrict__ woaT, float* __restrict__ boa) {
    int bid = blockIdx.x;
    int t = threadIdx.x;

    if (bid < LNQ_END) {
        ln_row(query + (size_t)bid * DMODEL, ln_q_s, ln_q_b,
               qbf + (size_t)bid * DMODEL);
        return;
    }
    if (bid < LNF_END) {
        int row = bid - LNQ_END;
        ln_row(feat + (size_t)row * DMODEL, ln_f_s, ln_f_b,
               fbf + (size_t)row * DMODEL);
        return;
    }
    if (bid < PREP_END) {
        int pb = bid - LNF_END;          // 0..5759
        int r = pb % 1920;
        int k = (pb / 1920) * 256 + t;   // 0..767
        if (r < 768) {
            wvalT[(size_t)r * DMODEL + k] = __float2bfloat16(Wv[(size_t)k * DMODEL + r]);
        } else if (r < 1536) {
            int n = r - 768;
            woutT[(size_t)n * DMODEL + k] = __float2bfloat16(Wo[(size_t)k * DMODEL + n]);
        } else if (r < 1792) {
            int n = r - 1536;
            float v = (n < 144) ? Wf[(size_t)k * 144 + n] : 0.f;
            woaT[(size_t)n * DMODEL + k] = __float2bfloat16(v);
        } else {
            int n = r - 1792;
            float v = (n < 72) ? Wa[(size_t)k * 72 + n] : 0.f;
            woaT[(size_t)(256 + n) * DMODEL + k] = __float2bfloat16(v);
        }
        if (pb == 0) {
            boa[t] = (t < 144) ? boff[t] : 0.f;
            if (t < 128) boa[256 + t] = (t < 72) ? batt[t] : 0.f;
        }
        return;
    }
    {   // dest: one block per batch, 256 threads x 4 elements
        int b = bid - PREP_END;
        const unsigned char* mb = (const unsigned char*)mraw;
        __shared__ int flagA, flagB;
        __shared__ int s[256];
        if (t == 0) { flagA = 0; flagB = 0; }
        __syncthreads();
        int la = 0, lb = 0;
        for (int j = t; j < 8192; j += 256) {
            if (mb[j]) { if ((j & 3) == 0) la = 1; else lb = 1; }
        }
        if (la) atomicOr(&flagA, 1);
        if (lb) atomicOr(&flagB, 1);
        __syncthreads();
        int a = flagA, bbf = flagB;
        int base = b << 10;
        int m[4], cnt = 0;
        #pragma unroll
        for (int e = 0; e < 4; e++) {
            int idx = base + t * 4 + e;
            int mm;
            if (a && !bbf)      mm = (((const int*)mraw)[idx] != 0);
            else if (!a && bbf) mm = (((const float*)mraw)[idx] != 0.0f);
            else                mm = (mb[idx] != 0);
            m[e] = mm;
            cnt += mm;
        }
        s[t] = cnt;
        __syncthreads();
        for (int off = 1; off < 256; off <<= 1) {
            int v = (t >= off) ? s[t - off] : 0;
            __syncthreads();
            s[t] += v;
            __syncthreads();
        }
        int T = s[255];
        int run = s[t] - cnt;            // masked count before this thread's span
        #pragma unroll
        for (int e = 0; e < 4; e++) {
            int i = t * 4 + e;
            if (m[e]) { dest[base + i] = run; run++; }
            else      { dest[base + i] = T + i - run; }
        }
    }
}

// -------------------- MSDeformAttn sampling (bf16 value) -------------------
__global__ __launch_bounds__(128) void msda_sample_kernel(
    const float* __restrict__ oa,
    const __nv_bfloat16* __restrict__ value,
    __nv_bfloat16* __restrict__ out) {
    __shared__ float sl[72];
    __shared__ float saw[72];
    __shared__ int   srow[72][4];
    __shared__ float swgt[72][4];

    int row = blockIdx.x;
    int b = row >> 10, q = row & 1023;
    int t = threadIdx.x;

    if (t < 72) sl[t] = oa[(size_t)row * OA_LD + 256 + t];
    __syncthreads();

    if (t < 6) {
        float mx = -1e30f;
        #pragma unroll
        for (int s = 0; s < 12; s++) mx = fmaxf(mx, sl[t * 12 + s]);
        float e[12], sum = 0.f;
        #pragma unroll
        for (int s = 0; s < 12; s++) { e[s] = expf(sl[t * 12 + s] - mx); sum += e[s]; }
        float inv = 1.f / sum;
        #pragma unroll
        for (int s = 0; s < 12; s++) saw[t * 12 + s] = e[s] * inv;
    }
    __syncthreads();

    if (t < 72) {
        int h = t / 12, s = t % 12, lvl = s >> 2, p = s & 3;
        const int DIMS[3] = {64, 32, 16};
        const int ST[3]   = {0, 4096, 5120};
        int Hd = DIMS[lvl], Wd = DIMS[lvl], st = ST[lvl];
        float refx = ((q & 31) + 0.5f) * (1.0f / 32.0f);
        float refy = ((q >> 5) + 0.5f) * (1.0f / 32.0f);
        size_t obase = (size_t)row * OA_LD + h * 24 + lvl * 8 + p * 2;
        float ox = oa[obase + 0];
        float oy = oa[obase + 1];
        float x = (refx + ox / (float)Wd) * (float)Wd - 0.5f;
        float y = (refy + oy / (float)Hd) * (float)Hd - 0.5f;
        float x0 = floorf(x), y0 = floorf(y);
        float wx1 = x - x0, wy1 = y - y0;
        int x0i = (int)x0, y0i = (int)y0;
        float aw = saw[t];
        #pragma unroll
        for (int c = 0; c < 4; c++) {
            int dx = c & 1, dy = c >> 1;
            int xi = x0i + dx, yi = y0i + dy;
            bool valid = (xi >= 0) && (xi < Wd) && (yi >= 0) && (yi < Hd);
            float wx = dx ? wx1 : 1.f - wx1;
            float wy = dy ? wy1 : 1.f - wy1;
            srow[t][c] = valid ? (st + yi * Wd + xi) : -1;
            swgt[t][c] = aw * wx * wy;
        }
    }
    __syncthreads();

    int d = t;
    const __nv_bfloat16* vb = value + (size_t)b * LIN * DMODEL + d;
    __nv_bfloat16* orow = out + (size_t)row * DMODEL + d;
    #pragma unroll 1
    for (int h = 0; h < NHEAD; h++) {
        float acc = 0.f;
        const __nv_bfloat16* vh = vb + h * DHEAD;
        #pragma unroll 1
        for (int s = 0; s < 12; s++) {
            int tt = h * 12 + s;
            #pragma unroll
            for (int c = 0; c < 4; c++) {
                int r = srow[tt][c];
                if (r >= 0) acc += swgt[tt][c] * __bfloat162float(vh[(size_t)r * DMODEL]);
            }
        }
        orow[h * DHEAD] = __float2bfloat16(acc);
    }
}

// -------------------- launch -----------------------------------------------
extern "C" void kernel_launch(void* const* d_in, const int* in_sizes, int n_in,
                              void* d_out, int out_size) {
    const float* query  = (const float*)d_in[0];
    const float* feat   = (const float*)d_in[1];
    const void*  mask   = d_in[2];
    const float* ln_q_s = (const float*)d_in[3];
    const float* ln_q_b = (const float*)d_in[4];
    const float* ln_f_s = (const float*)d_in[5];
    const float* ln_f_b = (const float*)d_in[6];
    const float* W_val  = (const float*)d_in[7];
    const float* b_val  = (const float*)d_in[8];
    const float* W_off  = (const float*)d_in[9];
    const float* b_off  = (const float*)d_in[10];
    const float* W_attn = (const float*)d_in[11];
    const float* b_attn = (const float*)d_in[12];
    const float* W_out  = (const float*)d_in[13];
    const float* b_out  = (const float*)d_in[14];
    const float* gamma  = (const float*)d_in[15];
    float* out = (float*)d_out;

    __nv_bfloat16 *qbf, *fbf, *valb, *sampb, *wvalT, *woutT, *woaT;
    float *oa_s, *boa;
    int* dest_s;
    cudaGetSymbolAddress((void**)&qbf,    g_qbf);
    cudaGetSymbolAddress((void**)&fbf,    g_fbf);
    cudaGetSymbolAddress((void**)&valb,   g_valueb);
    cudaGetSymbolAddress((void**)&oa_s,   g_oa);
    cudaGetSymbolAddress((void**)&sampb,  g_sampb);
    cudaGetSymbolAddress((void**)&dest_s, g_dest);
    cudaGetSymbolAddress((void**)&wvalT,  g_wvalT);
    cudaGetSymbolAddress((void**)&woutT,  g_woutT);
    cudaGetSymbolAddress((void**)&woaT,   g_woaT);
    cudaGetSymbolAddress((void**)&boa,    g_boa);

    // 1: everything independent — LNq, LNf, dest, weight prep
    misc_kernel<<<DEST_END, 256>>>(query, feat, mask,
                                   ln_q_s, ln_q_b, ln_f_s, ln_f_b,
                                   W_val, W_out, W_off, W_attn, b_off, b_attn,
                                   qbf, fbf, dest_s, wvalT, woutT, woaT, boa);

    // 2: value GEMM (43008x768x768 -> bf16) + oa GEMM (8192x384x768 -> f32)
    big_gemm<<<dim3(6, 336 + 64), 256>>>(fbf, wvalT, b_val, valb,
                                         qbf, woaT, boa, oa_s);

    // 3: sampling
    msda_sample_kernel<<<NQROWS, 128>>>(oa_s, valb, sampb);

    // 4: fused out GEMM: out[dest] = query + gamma*(samp @ W_out + b_out)
    out_gemm<<<dim3(6, NQROWS / 128), 256>>>(sampb, woutT, b_out, out,
                                             query, gamma, dest_s);
}

// round 13
// speedup vs baseline: 1.1490x; 1.0204x over previous
#include <cuda_runtime.h>
#include <cuda_bf16.h>
#include <cstdint>
#include <cstddef>

// ---------------------------------------------------------------------------
// SelectiveViTAdapter: LN(q), LN(f) -> MSDeformAttn -> gamma residual -> stable
// mask-descending sort gather.
// 4 launches: misc(LNq+LNf+dest+prep) -> bigGEMM(value+oa) -> sampler ->
// outGEMM(fused residual+scatter).  mma.sync bf16 only.
// Round 13: 3-stage cp.async pipeline, ONE __syncthreads per K-iteration.
// ---------------------------------------------------------------------------

#define BATCH 8
#define DMODEL 768
#define NHEAD 6
#define DHEAD 128
#define LQ 1024
#define LIN 5376
#define NQROWS (BATCH * LQ)      // 8192
#define NFROWS (BATCH * LIN)     // 43008
#define OA_LD 384                // combined off(256) + attn(128) padded cols

// -------------------- scratch (static device globals) ----------------------
__device__ __nv_bfloat16 g_qbf[NQROWS * DMODEL];
__device__ __nv_bfloat16 g_fbf[NFROWS * DMODEL];
__device__ __nv_bfloat16 g_valueb[NFROWS * DMODEL];
__device__ float         g_oa[NQROWS * OA_LD];       // off cols [0,144); logits [256,328)
__device__ __nv_bfloat16 g_sampb[NQROWS * DMODEL];
__device__ int           g_dest[NQROWS];
__device__ __nv_bfloat16 g_wvalT[DMODEL * DMODEL];
__device__ __nv_bfloat16 g_woutT[DMODEL * DMODEL];
__device__ __nv_bfloat16 g_woaT[OA_LD * DMODEL];
__device__ float         g_boa[OA_LD];

// -------------------- PTX helpers ------------------------------------------
__device__ __forceinline__ uint32_t smem_u32(const void* p) {
    uint32_t a;
    asm("{ .reg .u64 t; cvta.to.shared.u64 t, %1; cvt.u32.u64 %0, t; }" : "=r"(a) : "l"(p));
    return a;
}
#define CP_ASYNC16(dst, src) asm volatile("cp.async.cg.shared.global [%0], [%1], 16;" :: "r"(dst), "l"(src) : "memory")
#define CP_COMMIT()          asm volatile("cp.async.commit_group;" ::: "memory")
#define CP_WAIT(n)           asm volatile("cp.async.wait_group %0;" :: "n"(n) : "memory")
#define LDSM4(r, a) asm volatile("ldmatrix.sync.aligned.m8n8.x4.shared.b16 {%0,%1,%2,%3}, [%4];" \
    : "=r"((r)[0]), "=r"((r)[1]), "=r"((r)[2]), "=r"((r)[3]) : "r"(a))

__device__ __forceinline__ void mma16816(float* c, const uint32_t* a, uint32_t b0, uint32_t b1) {
    asm volatile(
        "mma.sync.aligned.m16n8k16.row.col.f32.bf16.bf16.f32 "
        "{%0,%1,%2,%3}, {%4,%5,%6,%7}, {%8,%9}, {%0,%1,%2,%3};"
        : "+f"(c[0]), "+f"(c[1]), "+f"(c[2]), "+f"(c[3])
        : "r"(a[0]), "r"(a[1]), "r"(a[2]), "r"(a[3]), "r"(b0), "r"(b1));
}
// Swizzled smem offset for [rows x 32 bf16] tiles (64B rows, 16B chunks).
__device__ __forceinline__ uint32_t sw_off(int r, int c) {
    return (uint32_t)(r * 64 + ((c ^ ((r >> 1) & 3)) << 4));
}

// -------------------- shared GEMM mainloop (3-stage) ------------------------
// acc[4][4][4] += A[128 x 768] @ B[128 x 768]^T tile product.
// smbuf: 48KB triple-buffered (16KB/stage: A 8K + B 8K). 256 threads,
// 8 warps (2x4), 64x32 warp tile. ONE __syncthreads per iteration:
//   wait(stage it landed) -> sync (publish + all warps done with it-1)
//   -> prefetch stage it+2 -> compute stage it.
__device__ __forceinline__ void gemm_mainloop(
    const __nv_bfloat16* __restrict__ Ag, const __nv_bfloat16* __restrict__ Bg,
    char* smbuf, float acc[4][4][4]) {
    uint32_t sb = smem_u32(smbuf);
    int tid = threadIdx.x, wid = tid >> 5, lane = tid & 31;
    int wm = (wid >> 2) * 64, wn = (wid & 3) * 32;
    int lr0 = tid >> 2, lc = tid & 3;
    int lr1 = lr0 + 64;
    uint32_t dA0 = sw_off(lr0, lc), dA1 = sw_off(lr1, lc);

    // prologue: stages 0, 1
    #pragma unroll
    for (int p = 0; p < 2; p++) {
        uint32_t stg = sb + (uint32_t)p * 16384;
        int k0 = p * 32;
        CP_ASYNC16(stg + dA0,        Ag + (size_t)lr0 * DMODEL + k0 + lc * 8);
        CP_ASYNC16(stg + dA1,        Ag + (size_t)lr1 * DMODEL + k0 + lc * 8);
        CP_ASYNC16(stg + 8192 + dA0, Bg + (size_t)lr0 * DMODEL + k0 + lc * 8);
        CP_ASYNC16(stg + 8192 + dA1, Bg + (size_t)lr1 * DMODEL + k0 + lc * 8);
        CP_COMMIT();
    }

    int sidx = 0;                         // stage index of iteration `it` (mod 3)
    for (int it = 0; it < 24; ++it) {
        if (it < 23) { CP_WAIT(1); } else { CP_WAIT(0); }
        __syncthreads();
        if (it + 2 < 24) {
            int ps = sidx + 2; if (ps >= 3) ps -= 3;
            uint32_t stg = sb + (uint32_t)ps * 16384;
            int k0 = (it + 2) * 32;
            CP_ASYNC16(stg + dA0,        Ag + (size_t)lr0 * DMODEL + k0 + lc * 8);
            CP_ASYNC16(stg + dA1,        Ag + (size_t)lr1 * DMODEL + k0 + lc * 8);
            CP_ASYNC16(stg + 8192 + dA0, Bg + (size_t)lr0 * DMODEL + k0 + lc * 8);
            CP_ASYNC16(stg + 8192 + dA1, Bg + (size_t)lr1 * DMODEL + k0 + lc * 8);
            CP_COMMIT();
        }

        uint32_t aB = sb + (uint32_t)sidx * 16384;
        uint32_t bB = aB + 8192;
        #pragma unroll
        for (int ks = 0; ks < 2; ks++) {
            uint32_t ar[4][4], br[2][4];
            #pragma unroll
            for (int mi = 0; mi < 4; mi++) {
                int row = wm + mi * 16 + (lane & 15);
                int c = ks * 2 + (lane >> 4);
                LDSM4(ar[mi], aB + sw_off(row, c));
            }
            #pragma unroll
            for (int nb = 0; nb < 2; nb++) {
                int row = wn + nb * 16 + (lane & 7) + ((lane & 16) >> 1);
                int c = ks * 2 + ((lane & 8) >> 3);
                LDSM4(br[nb], bB + sw_off(row, c));
            }
            #pragma unroll
            for (int mi = 0; mi < 4; mi++)
                #pragma unroll
                for (int ni = 0; ni < 4; ni++)
                    mma16816(acc[mi][ni], ar[mi],
                             br[ni >> 1][(ni & 1) * 2], br[ni >> 1][(ni & 1) * 2 + 1]);
        }
        if (++sidx == 3) sidx = 0;
    }
}

// -------------------- big GEMM: value + oa in one launch --------------------
// blockIdx.y < 336: value tile (C bf16 = fbf @ wvalT^T + b_val, ldc 768)
// blockIdx.y >= 336 && blockIdx.x < 3: oa tile (C f32 = qbf @ woaT^T + boa, ldc 384)
__global__ __launch_bounds__(256) void big_gemm(
    const __nv_bfloat16* __restrict__ Afv, const __nv_bfloat16* __restrict__ Bfv,
    const float* __restrict__ bv, __nv_bfloat16* __restrict__ Cv,
    const __nv_bfloat16* __restrict__ Aoa, const __nv_bfloat16* __restrict__ Boa,
    const float* __restrict__ boa, float* __restrict__ Coa) {
    __shared__ __align__(128) char smbuf[3 * 16384];
    int isOA = (blockIdx.y >= 336);
    if (isOA && blockIdx.x >= 3) return;

    int by = isOA ? (blockIdx.y - 336) : blockIdx.y;
    int m0 = by * 128, n0 = blockIdx.x * 128;
    const __nv_bfloat16* Ag = (isOA ? Aoa : Afv) + (size_t)m0 * DMODEL;
    const __nv_bfloat16* Bg = (isOA ? Boa : Bfv) + (size_t)n0 * DMODEL;

    float acc[4][4][4];
    #pragma unroll
    for (int i = 0; i < 4; i++)
        #pragma unroll
        for (int j = 0; j < 4; j++)
            #pragma unroll
            for (int k = 0; k < 4; k++) acc[i][j][k] = 0.f;

    gemm_mainloop(Ag, Bg, smbuf, acc);

    int wid = threadIdx.x >> 5, lane = threadIdx.x & 31;
    int wm = (wid >> 2) * 64, wn = (wid & 3) * 32;
    const float* bias = isOA ? boa : bv;
    #pragma unroll
    for (int mi = 0; mi < 4; mi++) {
        int row = m0 + wm + mi * 16 + (lane >> 2);
        #pragma unroll
        for (int ni = 0; ni < 4; ni++) {
            int col = n0 + wn + ni * 8 + (lane & 3) * 2;
            float b0 = bias[col], b1 = bias[col + 1];
            if (!isOA) {
                __nv_bfloat162 v0 = __floats2bfloat162_rn(acc[mi][ni][0] + b0,
                                                          acc[mi][ni][1] + b1);
                __nv_bfloat162 v1 = __floats2bfloat162_rn(acc[mi][ni][2] + b0,
                                                          acc[mi][ni][3] + b1);
                *(__nv_bfloat162*)(Cv + (size_t)row * DMODEL + col) = v0;
                *(__nv_bfloat162*)(Cv + (size_t)(row + 8) * DMODEL + col) = v1;
            } else {
                float2 v0 = { acc[mi][ni][0] + b0, acc[mi][ni][1] + b1 };
                float2 v1 = { acc[mi][ni][2] + b0, acc[mi][ni][3] + b1 };
                *(float2*)(Coa + (size_t)row * OA_LD + col) = v0;
                *(float2*)(Coa + (size_t)(row + 8) * OA_LD + col) = v1;
            }
        }
    }
}

// -------------------- out GEMM: fused residual + scatter --------------------
__global__ __launch_bounds__(256) void out_gemm(
    const __nv_bfloat16* __restrict__ A, const __nv_bfloat16* __restrict__ Bt,
    const float* __restrict__ bias, float* __restrict__ C,
    const float* __restrict__ query, const float* __restrict__ gamma,
    const int* __restrict__ dest) {
    __shared__ __align__(128) char smbuf[3 * 16384];
    int m0 = blockIdx.y * 128, n0 = blockIdx.x * 128;
    const __nv_bfloat16* Ag = A + (size_t)m0 * DMODEL;
    const __nv_bfloat16* Bg = Bt + (size_t)n0 * DMODEL;

    float acc[4][4][4];
    #pragma unroll
    for (int i = 0; i < 4; i++)
        #pragma unroll
        for (int j = 0; j < 4; j++)
            #pragma unroll
            for (int k = 0; k < 4; k++) acc[i][j][k] = 0.f;

    gemm_mainloop(Ag, Bg, smbuf, acc);

    int wid = threadIdx.x >> 5, lane = threadIdx.x & 31;
    int wm = (wid >> 2) * 64, wn = (wid & 3) * 32;
    #pragma unroll
    for (int mi = 0; mi < 4; mi++) {
        int row = m0 + wm + mi * 16 + (lane >> 2);
        #pragma unroll
        for (int ni = 0; ni < 4; ni++) {
            int col = n0 + wn + ni * 8 + (lane & 3) * 2;
            float b0 = bias[col], b1 = bias[col + 1];
            float g0 = gamma[col], g1 = gamma[col + 1];
            int r0 = row, r1 = row + 8;
            int d0 = ((r0 >> 10) << 10) + dest[r0];
            int d1 = ((r1 >> 10) << 10) + dest[r1];
            float2 q0 = *(const float2*)(query + (size_t)r0 * DMODEL + col);
            float2 q1 = *(const float2*)(query + (size_t)r1 * DMODEL + col);
            float2 v0 = { q0.x + g0 * (acc[mi][ni][0] + b0),
                          q0.y + g1 * (acc[mi][ni][1] + b1) };
            float2 v1 = { q1.x + g0 * (acc[mi][ni][2] + b0),
                          q1.y + g1 * (acc[mi][ni][3] + b1) };
            *(float2*)(C + (size_t)d0 * DMODEL + col) = v0;
            *(float2*)(C + (size_t)d1 * DMODEL + col) = v1;
        }
    }
}

// -------------------- misc: LN(q) + LN(f) + dest + weight prep -------------
#define LNQ_END 8192
#define LNF_END 51200
#define PREP_END 56960
#define DEST_END 56968

__device__ __forceinline__ void ln_row(const float* xr, const float* sc,
                                       const float* bi, __nv_bfloat16* yr) {
    int t = threadIdx.x;
    float v0 = xr[t], v1 = xr[t + 256], v2 = xr[t + 512];
    float sum = v0 + v1 + v2;
    float sq  = v0 * v0 + v1 * v1 + v2 * v2;
    #pragma unroll
    for (int o = 16; o > 0; o >>= 1) {
        sum += __shfl_xor_sync(0xffffffffu, sum, o);
        sq  += __shfl_xor_sync(0xffffffffu, sq,  o);
    }
    __shared__ float ssum[8], ssq[8], smean, sinv;
    if ((t & 31) == 0) { ssum[t >> 5] = sum; ssq[t >> 5] = sq; }
    __syncthreads();
    if (t == 0) {
        float S = 0.f, Q = 0.f;
        #pragma unroll
        for (int w = 0; w < 8; w++) { S += ssum[w]; Q += ssq[w]; }
        float mean = S * (1.0f / DMODEL);
        float var  = Q * (1.0f / DMODEL) - mean * mean;
        smean = mean;
        sinv  = rsqrtf(var + 1e-6f);
    }
    __syncthreads();
    float mean = smean, inv = sinv;
    yr[t]       = __float2bfloat16((v0 - mean) * inv * sc[t]       + bi[t]);
    yr[t + 256] = __float2bfloat16((v1 - mean) * inv * sc[t + 256] + bi[t + 256]);
    yr[t + 512] = __float2bfloat16((v2 - mean) * inv * sc[t + 512] + bi[t + 512]);
}

__global__ __launch_bounds__(256) void misc_kernel(
    const float* __restrict__ query, const float* __restrict__ feat,
    const void* __restrict__ mraw,
    const float* __restrict__ ln_q_s, const float* __restrict__ ln_q_b,
    const float* __restrict__ ln_f_s, const float* __restrict__ ln_f_b,
    const float* __restrict__ Wv, const float* __restrict__ Wo,
    const float* __restrict__ Wf, const float* __restrict__ Wa,
    const float* __restrict__ boff, const float* __restrict__ batt,
    __nv_bfloat16* __restrict__ qbf, __nv_bfloat16* __restrict__ fbf,
    int* __restrict__ dest,
    __nv_bfloat16* __restrict__ wvalT, __nv_bfloat16* __restrict__ woutT,
    __nv_bfloat16* __restrict__ woaT, float* __restrict__ boa) {
    int bid = blockIdx.x;
    int t = threadIdx.x;

    if (bid < LNQ_END) {
        ln_row(query + (size_t)bid * DMODEL, ln_q_s, ln_q_b,
               qbf + (size_t)bid * DMODEL);
        return;
    }
    if (bid < LNF_END) {
        int row = bid - LNQ_END;
        ln_row(feat + (size_t)row * DMODEL, ln_f_s, ln_f_b,
               fbf + (size_t)row * DMODEL);
        return;
    }
    if (bid < PREP_END) {
        int pb = bid - LNF_END;          // 0..5759
        int r = pb % 1920;
        int k = (pb / 1920) * 256 + t;   // 0..767
        if (r < 768) {
            wvalT[(size_t)r * DMODEL + k] = __float2bfloat16(Wv[(size_t)k * DMODEL + r]);
        } else if (r < 1536) {
            int n = r - 768;
            woutT[(size_t)n * DMODEL + k] = __float2bfloat16(Wo[(size_t)k * DMODEL + n]);
        } else if (r < 1792) {
            int n = r - 1536;
            float v = (n < 144) ? Wf[(size_t)k * 144 + n] : 0.f;
            woaT[(size_t)n * DMODEL + k] = __float2bfloat16(v);
        } else {
            int n = r - 1792;
            float v = (n < 72) ? Wa[(size_t)k * 72 + n] : 0.f;
            woaT[(size_t)(256 + n) * DMODEL + k] = __float2bfloat16(v);
        }
        if (pb == 0) {
            boa[t] = (t < 144) ? boff[t] : 0.f;
            if (t < 128) boa[256 + t] = (t < 72) ? batt[t] : 0.f;
        }
        return;
    }
    {   // dest: one block per batch, 256 threads x 4 elements
        int b = bid - PREP_END;
        const unsigned char* mb = (const unsigned char*)mraw;
        __shared__ int flagA, flagB;
        __shared__ int s[256];
        if (t == 0) { flagA = 0; flagB = 0; }
        __syncthreads();
        int la = 0, lb = 0;
        for (int j = t; j < 8192; j += 256) {
            if (mb[j]) { if ((j & 3) == 0) la = 1; else lb = 1; }
        }
        if (la) atomicOr(&flagA, 1);
        if (lb) atomicOr(&flagB, 1);
        __syncthreads();
        int a = flagA, bbf = flagB;
        int base = b << 10;
        int m[4], cnt = 0;
        #pragma unroll
        for (int e = 0; e < 4; e++) {
            int idx = base + t * 4 + e;
            int mm;
            if (a && !bbf)      mm = (((const int*)mraw)[idx] != 0);
            else if (!a && bbf) mm = (((const float*)mraw)[idx] != 0.0f);
            else                mm = (mb[idx] != 0);
            m[e] = mm;
            cnt += mm;
        }
        s[t] = cnt;
        __syncthreads();
        for (int off = 1; off < 256; off <<= 1) {
            int v = (t >= off) ? s[t - off] : 0;
            __syncthreads();
            s[t] += v;
            __syncthreads();
        }
        int T = s[255];
        int run = s[t] - cnt;
        #pragma unroll
        for (int e = 0; e < 4; e++) {
            int i = t * 4 + e;
            if (m[e]) { dest[base + i] = run; run++; }
            else      { dest[base + i] = T + i - run; }
        }
    }
}

// -------------------- MSDeformAttn sampling (bf16 value) -------------------
__global__ __launch_bounds__(128) void msda_sample_kernel(
    const float* __restrict__ oa,
    const __nv_bfloat16* __restrict__ value,
    __nv_bfloat16* __restrict__ out) {
    __shared__ float sl[72];
    __shared__ float saw[72];
    __shared__ int   srow[72][4];
    __shared__ float swgt[72][4];

    int row = blockIdx.x;
    int b = row >> 10, q = row & 1023;
    int t = threadIdx.x;

    if (t < 72) sl[t] = oa[(size_t)row * OA_LD + 256 + t];
    __syncthreads();

    if (t < 6) {
        float mx = -1e30f;
        #pragma unroll
        for (int s = 0; s < 12; s++) mx = fmaxf(mx, sl[t * 12 + s]);
        float e[12], sum = 0.f;
        #pragma unroll
        for (int s = 0; s < 12; s++) { e[s] = expf(sl[t * 12 + s] - mx); sum += e[s]; }
        float inv = 1.f / sum;
        #pragma unroll
        for (int s = 0; s < 12; s++) saw[t * 12 + s] = e[s] * inv;
    }
    __syncthreads();

    if (t < 72) {
        int h = t / 12, s = t % 12, lvl = s >> 2, p = s & 3;
        const int DIMS[3] = {64, 32, 16};
        const int ST[3]   = {0, 4096, 5120};
        int Hd = DIMS[lvl], Wd = DIMS[lvl], st = ST[lvl];
        float refx = ((q & 31) + 0.5f) * (1.0f / 32.0f);
        float refy = ((q >> 5) + 0.5f) * (1.0f / 32.0f);
        size_t obase = (size_t)row * OA_LD + h * 24 + lvl * 8 + p * 2;
        float ox = oa[obase + 0];
        float oy = oa[obase + 1];
        float x = (refx + ox / (float)Wd) * (float)Wd - 0.5f;
        float y = (refy + oy / (float)Hd) * (float)Hd - 0.5f;
        float x0 = floorf(x), y0 = floorf(y);
        float wx1 = x - x0, wy1 = y - y0;
        int x0i = (int)x0, y0i = (int)y0;
        float aw = saw[t];
        #pragma unroll
        for (int c = 0; c < 4; c++) {
            int dx = c & 1, dy = c >> 1;
            int xi = x0i + dx, yi = y0i + dy;
            bool valid = (xi >= 0) && (xi < Wd) && (yi >= 0) && (yi < Hd);
            float wx = dx ? wx1 : 1.f - wx1;
            float wy = dy ? wy1 : 1.f - wy1;
            srow[t][c] = valid ? (st + yi * Wd + xi) : -1;
            swgt[t][c] = aw * wx * wy;
        }
    }
    __syncthreads();

    int d = t;
    const __nv_bfloat16* vb = value + (size_t)b * LIN * DMODEL + d;
    __nv_bfloat16* orow = out + (size_t)row * DMODEL + d;
    #pragma unroll 1
    for (int h = 0; h < NHEAD; h++) {
        float acc = 0.f;
        const __nv_bfloat16* vh = vb + h * DHEAD;
        #pragma unroll 1
        for (int s = 0; s < 12; s++) {
            int tt = h * 12 + s;
            #pragma unroll
            for (int c = 0; c < 4; c++) {
                int r = srow[tt][c];
                if (r >= 0) acc += swgt[tt][c] * __bfloat162float(vh[(size_t)r * DMODEL]);
            }
        }
        orow[h * DHEAD] = __float2bfloat16(acc);
    }
}

// -------------------- launch -----------------------------------------------
extern "C" void kernel_launch(void* const* d_in, const int* in_sizes, int n_in,
                              void* d_out, int out_size) {
    const float* query  = (const float*)d_in[0];
    const float* feat   = (const float*)d_in[1];
    const void*  mask   = d_in[2];
    const float* ln_q_s = (const float*)d_in[3];
    const float* ln_q_b = (const float*)d_in[4];
    const float* ln_f_s = (const float*)d_in[5];
    const float* ln_f_b = (const float*)d_in[6];
    const float* W_val  = (const float*)d_in[7];
    const float* b_val  = (const float*)d_in[8];
    const float* W_off  = (const float*)d_in[9];
    const float* b_off  = (const float*)d_in[10];
    const float* W_attn = (const float*)d_in[11];
    const float* b_attn = (const float*)d_in[12];
    const float* W_out  = (const float*)d_in[13];
    const float* b_out  = (const float*)d_in[14];
    const float* gamma  = (const float*)d_in[15];
    float* out = (float*)d_out;

    __nv_bfloat16 *qbf, *fbf, *valb, *sampb, *wvalT, *woutT, *woaT;
    float *oa_s, *boa;
    int* dest_s;
    cudaGetSymbolAddress((void**)&qbf,    g_qbf);
    cudaGetSymbolAddress((void**)&fbf,    g_fbf);
    cudaGetSymbolAddress((void**)&valb,   g_valueb);
    cudaGetSymbolAddress((void**)&oa_s,   g_oa);
    cudaGetSymbolAddress((void**)&sampb,  g_sampb);
    cudaGetSymbolAddress((void**)&dest_s, g_dest);
    cudaGetSymbolAddress((void**)&wvalT,  g_wvalT);
    cudaGetSymbolAddress((void**)&woutT,  g_woutT);
    cudaGetSymbolAddress((void**)&woaT,   g_woaT);
    cudaGetSymbolAddress((void**)&boa,    g_boa);

    // 1: everything independent — LNq, LNf, dest, weight prep
    misc_kernel<<<DEST_END, 256>>>(query, feat, mask,
                                   ln_q_s, ln_q_b, ln_f_s, ln_f_b,
                                   W_val, W_out, W_off, W_attn, b_off, b_attn,
                                   qbf, fbf, dest_s, wvalT, woutT, woaT, boa);

    // 2: value GEMM (43008x768x768 -> bf16) + oa GEMM (8192x384x768 -> f32)
    big_gemm<<<dim3(6, 336 + 64), 256>>>(fbf, wvalT, b_val, valb,
                                         qbf, woaT, boa, oa_s);

    // 3: sampling
    msda_sample_kernel<<<NQROWS, 128>>>(oa_s, valb, sampb);

    // 4: fused out GEMM: out[dest] = query + gamma*(samp @ W_out + b_out)
    out_gemm<<<dim3(6, NQROWS / 128), 256>>>(sampb, woutT, b_out, out,
                                             query, gamma, dest_s);
}

// round 15
// speedup vs baseline: 1.1775x; 1.0248x over previous
#include <cuda_runtime.h>
#include <cuda_bf16.h>
#include <cstdint>
#include <cstddef>

// ---------------------------------------------------------------------------
// SelectiveViTAdapter: LN(q), LN(f) -> MSDeformAttn -> gamma residual -> stable
// mask-descending sort gather.
// 4 launches: misc(LNq+LNf+dest+prep) -> bigGEMM(value+oa) -> sampler ->
// outGEMM(fused residual+scatter).  mma.sync bf16 only.
// Round 15: 4 warps/CTA, 2x2 warp grid, 64x64 warp tiles (halved smem
// crossbar traffic) with CORRECTED 64B-row loader indexing (r14 bug:
// loader assumed 128B rows -> stage overflow + OOB global reads).
// ---------------------------------------------------------------------------

#define BATCH 8
#define DMODEL 768
#define NHEAD 6
#define DHEAD 128
#define LQ 1024
#define LIN 5376
#define NQROWS (BATCH * LQ)      // 8192
#define NFROWS (BATCH * LIN)     // 43008
#define OA_LD 384                // combined off(256) + attn(128) padded cols

// -------------------- scratch (static device globals) ----------------------
__device__ __nv_bfloat16 g_qbf[NQROWS * DMODEL];
__device__ __nv_bfloat16 g_fbf[NFROWS * DMODEL];
__device__ __nv_bfloat16 g_valueb[NFROWS * DMODEL];
__device__ float         g_oa[NQROWS * OA_LD];       // off cols [0,144); logits [256,328)
__device__ __nv_bfloat16 g_sampb[NQROWS * DMODEL];
__device__ int           g_dest[NQROWS];
__device__ __nv_bfloat16 g_wvalT[DMODEL * DMODEL];
__device__ __nv_bfloat16 g_woutT[DMODEL * DMODEL];
__device__ __nv_bfloat16 g_woaT[OA_LD * DMODEL];
__device__ float         g_boa[OA_LD];

// -------------------- PTX helpers ------------------------------------------
__device__ __forceinline__ uint32_t smem_u32(const void* p) {
    uint32_t a;
    asm("{ .reg .u64 t; cvta.to.shared.u64 t, %1; cvt.u32.u64 %0, t; }" : "=r"(a) : "l"(p));
    return a;
}
#define CP_ASYNC16(dst, src) asm volatile("cp.async.cg.shared.global [%0], [%1], 16;" :: "r"(dst), "l"(src) : "memory")
#define CP_COMMIT()          asm volatile("cp.async.commit_group;" ::: "memory")
#define CP_WAIT(n)           asm volatile("cp.async.wait_group %0;" :: "n"(n) : "memory")
#define LDSM4(r, a) asm volatile("ldmatrix.sync.aligned.m8n8.x4.shared.b16 {%0,%1,%2,%3}, [%4];" \
    : "=r"((r)[0]), "=r"((r)[1]), "=r"((r)[2]), "=r"((r)[3]) : "r"(a))

__device__ __forceinline__ void mma16816(float* c, const uint32_t* a, uint32_t b0, uint32_t b1) {
    asm volatile(
        "mma.sync.aligned.m16n8k16.row.col.f32.bf16.bf16.f32 "
        "{%0,%1,%2,%3}, {%4,%5,%6,%7}, {%8,%9}, {%0,%1,%2,%3};"
        : "+f"(c[0]), "+f"(c[1]), "+f"(c[2]), "+f"(c[3])
        : "r"(a[0]), "r"(a[1]), "r"(a[2]), "r"(a[3]), "r"(b0), "r"(b1));
}
// Swizzled smem offset for [rows x 32 bf16] tiles (64B rows, 16B chunks c in [0,4)).
__device__ __forceinline__ uint32_t sw_off(int r, int c) {
    return (uint32_t)(r * 64 + ((c ^ ((r >> 1) & 3)) << 4));
}

// -------------------- shared GEMM mainloop (3-stage, 4 warps) ---------------
// acc[4][8][4] += A[128 x 768] @ B[128 x 768]^T tile product.
// smbuf: 48KB triple-buffered (16KB/stage: A 8K + B 8K; 64B rows, 4 chunks/row).
// 128 threads, 4 warps (2x2), 64x64 warp tiles. One __syncthreads per iter.
// Loader: thread tid covers rows rb+32*jj (jj<4) at chunk c4 for A and B
// (8 cp.async/thread = 1024 chunks = 16KB). k-offset c4*8 <= 24, k0 <= 736.
__device__ __forceinline__ void gemm_mainloop(
    const __nv_bfloat16* __restrict__ Ag, const __nv_bfloat16* __restrict__ Bg,
    char* smbuf, float acc[4][8][4]) {
    uint32_t sb = smem_u32(smbuf);
    int tid = threadIdx.x, wid = tid >> 5, lane = tid & 31;
    int wm = (wid >> 1) * 64, wn = (wid & 1) * 64;
    int rb = tid >> 2, c4 = tid & 3;

    // prologue: stages 0, 1
    #pragma unroll
    for (int p = 0; p < 2; p++) {
        uint32_t stg = sb + (uint32_t)p * 16384;
        int k0 = p * 32;
        #pragma unroll
        for (int jj = 0; jj < 4; jj++) {
            int r = rb + jj * 32;
            uint32_t off = sw_off(r, c4);
            CP_ASYNC16(stg + off,        Ag + (size_t)r * DMODEL + k0 + c4 * 8);
            CP_ASYNC16(stg + 8192 + off, Bg + (size_t)r * DMODEL + k0 + c4 * 8);
        }
        CP_COMMIT();
    }

    int sidx = 0;
    for (int it = 0; it < 24; ++it) {
        if (it < 23) { CP_WAIT(1); } else { CP_WAIT(0); }
        __syncthreads();
        if (it + 2 < 24) {
            int ps = sidx + 2; if (ps >= 3) ps -= 3;
            uint32_t stg = sb + (uint32_t)ps * 16384;
            int k0 = (it + 2) * 32;
            #pragma unroll
            for (int jj = 0; jj < 4; jj++) {
                int r = rb + jj * 32;
                uint32_t off = sw_off(r, c4);
                CP_ASYNC16(stg + off,        Ag + (size_t)r * DMODEL + k0 + c4 * 8);
                CP_ASYNC16(stg + 8192 + off, Bg + (size_t)r * DMODEL + k0 + c4 * 8);
            }
            CP_COMMIT();
        }

        uint32_t aB = sb + (uint32_t)sidx * 16384;
        uint32_t bB = aB + 8192;
        #pragma unroll
        for (int ks = 0; ks < 2; ks++) {
            uint32_t ar[4][4], br[4][4];
            #pragma unroll
            for (int mi = 0; mi < 4; mi++) {
                int row = wm + mi * 16 + (lane & 15);
                int c = ks * 2 + (lane >> 4);
                LDSM4(ar[mi], aB + sw_off(row, c));
            }
            #pragma unroll
            for (int nb = 0; nb < 4; nb++) {
                int row = wn + nb * 16 + (lane & 7) + ((lane & 16) >> 1);
                int c = ks * 2 + ((lane & 8) >> 3);
                LDSM4(br[nb], bB + sw_off(row, c));
            }
            #pragma unroll
            for (int mi = 0; mi < 4; mi++)
                #pragma unroll
                for (int ni = 0; ni < 8; ni++)
                    mma16816(acc[mi][ni], ar[mi],
                             br[ni >> 1][(ni & 1) * 2], br[ni >> 1][(ni & 1) * 2 + 1]);
        }
        if (++sidx == 3) sidx = 0;
    }
}

// -------------------- big GEMM: value + oa in one launch --------------------
// blockIdx.y < 336: value tile (C bf16 = fbf @ wvalT^T + b_val, ldc 768)
// blockIdx.y >= 336 && blockIdx.x < 3: oa tile (C f32 = qbf @ woaT^T + boa, ldc 384)
__global__ __launch_bounds__(128) void big_gemm(
    const __nv_bfloat16* __restrict__ Afv, const __nv_bfloat16* __restrict__ Bfv,
    const float* __restrict__ bv, __nv_bfloat16* __restrict__ Cv,
    const __nv_bfloat16* __restrict__ Aoa, const __nv_bfloat16* __restrict__ Boa,
    const float* __restrict__ boa, float* __restrict__ Coa) {
    __shared__ __align__(128) char smbuf[3 * 16384];
    int isOA = (blockIdx.y >= 336);
    if (isOA && blockIdx.x >= 3) return;

    int by = isOA ? (blockIdx.y - 336) : blockIdx.y;
    int m0 = by * 128, n0 = blockIdx.x * 128;
    const __nv_bfloat16* Ag = (isOA ? Aoa : Afv) + (size_t)m0 * DMODEL;
    const __nv_bfloat16* Bg = (isOA ? Boa : Bfv) + (size_t)n0 * DMODEL;

    float acc[4][8][4];
    #pragma unroll
    for (int i = 0; i < 4; i++)
        #pragma unroll
        for (int j = 0; j < 8; j++)
            #pragma unroll
            for (int k = 0; k < 4; k++) acc[i][j][k] = 0.f;

    gemm_mainloop(Ag, Bg, smbuf, acc);

    int wid = threadIdx.x >> 5, lane = threadIdx.x & 31;
    int wm = (wid >> 1) * 64, wn = (wid & 1) * 64;
    const float* bias = isOA ? boa : bv;
    #pragma unroll
    for (int mi = 0; mi < 4; mi++) {
        int row = m0 + wm + mi * 16 + (lane >> 2);
        #pragma unroll
        for (int ni = 0; ni < 8; ni++) {
            int col = n0 + wn + ni * 8 + (lane & 3) * 2;
            float b0 = bias[col], b1 = bias[col + 1];
            if (!isOA) {
                __nv_bfloat162 v0 = __floats2bfloat162_rn(acc[mi][ni][0] + b0,
                                                          acc[mi][ni][1] + b1);
                __nv_bfloat162 v1 = __floats2bfloat162_rn(acc[mi][ni][2] + b0,
                                                          acc[mi][ni][3] + b1);
                *(__nv_bfloat162*)(Cv + (size_t)row * DMODEL + col) = v0;
                *(__nv_bfloat162*)(Cv + (size_t)(row + 8) * DMODEL + col) = v1;
            } else {
                float2 v0 = { acc[mi][ni][0] + b0, acc[mi][ni][1] + b1 };
                float2 v1 = { acc[mi][ni][2] + b0, acc[mi][ni][3] + b1 };
                *(float2*)(Coa + (size_t)row * OA_LD + col) = v0;
                *(float2*)(Coa + (size_t)(row + 8) * OA_LD + col) = v1;
            }
        }
    }
}

// -------------------- out GEMM: fused residual + scatter --------------------
__global__ __launch_bounds__(128) void out_gemm(
    const __nv_bfloat16* __restrict__ A, const __nv_bfloat16* __restrict__ Bt,
    const float* __restrict__ bias, float* __restrict__ C,
    const float* __restrict__ query, const float* __restrict__ gamma,
    const int* __restrict__ dest) {
    __shared__ __align__(128) char smbuf[3 * 16384];
    int m0 = blockIdx.y * 128, n0 = blockIdx.x * 128;
    const __nv_bfloat16* Ag = A + (size_t)m0 * DMODEL;
    const __nv_bfloat16* Bg = Bt + (size_t)n0 * DMODEL;

    float acc[4][8][4];
    #pragma unroll
    for (int i = 0; i < 4; i++)
        #pragma unroll
        for (int j = 0; j < 8; j++)
            #pragma unroll
            for (int k = 0; k < 4; k++) acc[i][j][k] = 0.f;

    gemm_mainloop(Ag, Bg, smbuf, acc);

    int wid = threadIdx.x >> 5, lane = threadIdx.x & 31;
    int wm = (wid >> 1) * 64, wn = (wid & 1) * 64;
    #pragma unroll
    for (int mi = 0; mi < 4; mi++) {
        int row = m0 + wm + mi * 16 + (lane >> 2);
        #pragma unroll
        for (int ni = 0; ni < 8; ni++) {
            int col = n0 + wn + ni * 8 + (lane & 3) * 2;
            float b0 = bias[col], b1 = bias[col + 1];
            float g0 = gamma[col], g1 = gamma[col + 1];
            int r0 = row, r1 = row + 8;
            int d0 = ((r0 >> 10) << 10) + dest[r0];
            int d1 = ((r1 >> 10) << 10) + dest[r1];
            float2 q0 = *(const float2*)(query + (size_t)r0 * DMODEL + col);
            float2 q1 = *(const float2*)(query + (size_t)r1 * DMODEL + col);
            float2 v0 = { q0.x + g0 * (acc[mi][ni][0] + b0),
                          q0.y + g1 * (acc[mi][ni][1] + b1) };
            float2 v1 = { q1.x + g0 * (acc[mi][ni][2] + b0),
                          q1.y + g1 * (acc[mi][ni][3] + b1) };
            *(float2*)(C + (size_t)d0 * DMODEL + col) = v0;
            *(float2*)(C + (size_t)d1 * DMODEL + col) = v1;
        }
    }
}

// -------------------- misc: LN(q) + LN(f) + dest + weight prep -------------
#define LNQ_END 8192
#define LNF_END 51200
#define PREP_END 56960
#define DEST_END 56968

__device__ __forceinline__ void ln_row(const float* xr, const float* sc,
                                       const float* bi, __nv_bfloat16* yr) {
    int t = threadIdx.x;
    float v0 = xr[t], v1 = xr[t + 256], v2 = xr[t + 512];
    float sum = v0 + v1 + v2;
    float sq  = v0 * v0 + v1 * v1 + v2 * v2;
    #pragma unroll
    for (int o = 16; o > 0; o >>= 1) {
        sum += __shfl_xor_sync(0xffffffffu, sum, o);
        sq  += __shfl_xor_sync(0xffffffffu, sq,  o);
    }
    __shared__ float ssum[8], ssq[8], smean, sinv;
    if ((t & 31) == 0) { ssum[t >> 5] = sum; ssq[t >> 5] = sq; }
    __syncthreads();
    if (t == 0) {
        float S = 0.f, Q = 0.f;
        #pragma unroll
        for (int w = 0; w < 8; w++) { S += ssum[w]; Q += ssq[w]; }
        float mean = S * (1.0f / DMODEL);
        float var  = Q * (1.0f / DMODEL) - mean * mean;
        smean = mean;
        sinv  = rsqrtf(var + 1e-6f);
    }
    __syncthreads();
    float mean = smean, inv = sinv;
    yr[t]       = __float2bfloat16((v0 - mean) * inv * sc[t]       + bi[t]);
    yr[t + 256] = __float2bfloat16((v1 - mean) * inv * sc[t + 256] + bi[t + 256]);
    yr[t + 512] = __float2bfloat16((v2 - mean) * inv * sc[t + 512] + bi[t + 512]);
}

__global__ __launch_bounds__(256) void misc_kernel(
    const float* __restrict__ query, const float* __restrict__ feat,
    const void* __restrict__ mraw,
    const float* __restrict__ ln_q_s, const float* __restrict__ ln_q_b,
    const float* __restrict__ ln_f_s, const float* __restrict__ ln_f_b,
    const float* __restrict__ Wv, const float* __restrict__ Wo,
    const float* __restrict__ Wf, const float* __restrict__ Wa,
    const float* __restrict__ boff, const float* __restrict__ batt,
    __nv_bfloat16* __restrict__ qbf, __nv_bfloat16* __restrict__ fbf,
    int* __restrict__ dest,
    __nv_bfloat16* __restrict__ wvalT, __nv_bfloat16* __restrict__ woutT,
    __nv_bfloat16* __restrict__ woaT, float* __restrict__ boa) {
    int bid = blockIdx.x;
    int t = threadIdx.x;

    if (bid < LNQ_END) {
        ln_row(query + (size_t)bid * DMODEL, ln_q_s, ln_q_b,
               qbf + (size_t)bid * DMODEL);
        return;
    }
    if (bid < LNF_END) {
        int row = bid - LNQ_END;
        ln_row(feat + (size_t)row * DMODEL, ln_f_s, ln_f_b,
               fbf + (size_t)row * DMODEL);
        return;
    }
    if (bid < PREP_END) {
        int pb = bid - LNF_END;          // 0..5759
        int r = pb % 1920;
        int k = (pb / 1920) * 256 + t;   // 0..767
        if (r < 768) {
            wvalT[(size_t)r * DMODEL + k] = __float2bfloat16(Wv[(size_t)k * DMODEL + r]);
        } else if (r < 1536) {
            int n = r - 768;
            woutT[(size_t)n * DMODEL + k] = __float2bfloat16(Wo[(size_t)k * DMODEL + n]);
        } else if (r < 1792) {
            int n = r - 1536;
            float v = (n < 144) ? Wf[(size_t)k * 144 + n] : 0.f;
            woaT[(size_t)n * DMODEL + k] = __float2bfloat16(v);
        } else {
            int n = r - 1792;
            float v = (n < 72) ? Wa[(size_t)k * 72 + n] : 0.f;
            woaT[(size_t)(256 + n) * DMODEL + k] = __float2bfloat16(v);
        }
        if (pb == 0) {
            boa[t] = (t < 144) ? boff[t] : 0.f;
            if (t < 128) boa[256 + t] = (t < 72) ? batt[t] : 0.f;
        }
        return;
    }
    {   // dest: one block per batch, 256 threads x 4 elements
        int b = bid - PREP_END;
        const unsigned char* mb = (const unsigned char*)mraw;
        __shared__ int flagA, flagB;
        __shared__ int s[256];
        if (t == 0) { flagA = 0; flagB = 0; }
        __syncthreads();
        int la = 0, lb = 0;
        for (int j = t; j < 8192; j += 256) {
            if (mb[j]) { if ((j & 3) == 0) la = 1; else lb = 1; }
        }
        if (la) atomicOr(&flagA, 1);
        if (lb) atomicOr(&flagB, 1);
        __syncthreads();
        int a = flagA, bbf = flagB;
        int base = b << 10;
        int m[4], cnt = 0;
        #pragma unroll
        for (int e = 0; e < 4; e++) {
            int idx = base + t * 4 + e;
            int mm;
            if (a && !bbf)      mm = (((const int*)mraw)[idx] != 0);
            else if (!a && bbf) mm = (((const float*)mraw)[idx] != 0.0f);
            else                mm = (mb[idx] != 0);
            m[e] = mm;
            cnt += mm;
        }
        s[t] = cnt;
        __syncthreads();
        for (int off = 1; off < 256; off <<= 1) {
            int v = (t >= off) ? s[t - off] : 0;
            __syncthreads();
            s[t] += v;
            __syncthreads();
        }
        int T = s[255];
        int run = s[t] - cnt;
        #pragma unroll
        for (int e = 0; e < 4; e++) {
            int i = t * 4 + e;
            if (m[e]) { dest[base + i] = run; run++; }
            else      { dest[base + i] = T + i - run; }
        }
    }
}

// -------------------- MSDeformAttn sampling (bf16 value) -------------------
__global__ __launch_bounds__(128) void msda_sample_kernel(
    const float* __restrict__ oa,
    const __nv_bfloat16* __restrict__ value,
    __nv_bfloat16* __restrict__ out) {
    __shared__ float sl[72];
    __shared__ float saw[72];
    __shared__ int   srow[72][4];
    __shared__ float swgt[72][4];

    int row = blockIdx.x;
    int b = row >> 10, q = row & 1023;
    int t = threadIdx.x;

    if (t < 72) sl[t] = oa[(size_t)row * OA_LD + 256 + t];
    __syncthreads();

    if (t < 6) {
        float mx = -1e30f;
        #pragma unroll
        for (int s = 0; s < 12; s++) mx = fmaxf(mx, sl[t * 12 + s]);
        float e[12], sum = 0.f;
        #pragma unroll
        for (int s = 0; s < 12; s++) { e[s] = expf(sl[t * 12 + s] - mx); sum += e[s]; }
        float inv = 1.f / sum;
        #pragma unroll
        for (int s = 0; s < 12; s++) saw[t * 12 + s] = e[s] * inv;
    }
    __syncthreads();

    if (t < 72) {
        int h = t / 12, s = t % 12, lvl = s >> 2, p = s & 3;
        const int DIMS[3] = {64, 32, 16};
        const int ST[3]   = {0, 4096, 5120};
        int Hd = DIMS[lvl], Wd = DIMS[lvl], st = ST[lvl];
        float refx = ((q & 31) + 0.5f) * (1.0f / 32.0f);
        float refy = ((q >> 5) + 0.5f) * (1.0f / 32.0f);
        size_t obase = (size_t)row * OA_LD + h * 24 + lvl * 8 + p * 2;
        float ox = oa[obase + 0];
        float oy = oa[obase + 1];
        float x = (refx + ox / (float)Wd) * (float)Wd - 0.5f;
        float y = (refy + oy / (float)Hd) * (float)Hd - 0.5f;
        float x0 = floorf(x), y0 = floorf(y);
        float wx1 = x - x0, wy1 = y - y0;
        int x0i = (int)x0, y0i = (int)y0;
        float aw = saw[t];
        #pragma unroll
        for (int c = 0; c < 4; c++) {
            int dx = c & 1, dy = c >> 1;
            int xi = x0i + dx, yi = y0i + dy;
            bool valid = (xi >= 0) && (xi < Wd) && (yi >= 0) && (yi < Hd);
            float wx = dx ? wx1 : 1.f - wx1;
            float wy = dy ? wy1 : 1.f - wy1;
            srow[t][c] = valid ? (st + yi * Wd + xi) : -1;
            swgt[t][c] = aw * wx * wy;
        }
    }
    __syncthreads();

    int d = t;
    const __nv_bfloat16* vb = value + (size_t)b * LIN * DMODEL + d;
    __nv_bfloat16* orow = out + (size_t)row * DMODEL + d;
    #pragma unroll 1
    for (int h = 0; h < NHEAD; h++) {
        float acc = 0.f;
        const __nv_bfloat16* vh = vb + h * DHEAD;
        #pragma unroll 1
        for (int s = 0; s < 12; s++) {
            int tt = h * 12 + s;
            #pragma unroll
            for (int c = 0; c < 4; c++) {
                int r = srow[tt][c];
                if (r >= 0) acc += swgt[tt][c] * __bfloat162float(vh[(size_t)r * DMODEL]);
            }
        }
        orow[h * DHEAD] = __float2bfloat16(acc);
    }
}

// -------------------- launch -----------------------------------------------
extern "C" void kernel_launch(void* const* d_in, const int* in_sizes, int n_in,
                              void* d_out, int out_size) {
    const float* query  = (const float*)d_in[0];
    const float* feat   = (const float*)d_in[1];
    const void*  mask   = d_in[2];
    const float* ln_q_s = (const float*)d_in[3];
    const float* ln_q_b = (const float*)d_in[4];
    const float* ln_f_s = (const float*)d_in[5];
    const float* ln_f_b = (const float*)d_in[6];
    const float* W_val  = (const float*)d_in[7];
    const float* b_val  = (const float*)d_in[8];
    const float* W_off  = (const float*)d_in[9];
    const float* b_off  = (const float*)d_in[10];
    const float* W_attn = (const float*)d_in[11];
    const float* b_attn = (const float*)d_in[12];
    const float* W_out  = (const float*)d_in[13];
    const float* b_out  = (const float*)d_in[14];
    const float* gamma  = (const float*)d_in[15];
    float* out = (float*)d_out;

    __nv_bfloat16 *qbf, *fbf, *valb, *sampb, *wvalT, *woutT, *woaT;
    float *oa_s, *boa;
    int* dest_s;
    cudaGetSymbolAddress((void**)&qbf,    g_qbf);
    cudaGetSymbolAddress((void**)&fbf,    g_fbf);
    cudaGetSymbolAddress((void**)&valb,   g_valueb);
    cudaGetSymbolAddress((void**)&oa_s,   g_oa);
    cudaGetSymbolAddress((void**)&sampb,  g_sampb);
    cudaGetSymbolAddress((void**)&dest_s, g_dest);
    cudaGetSymbolAddress((void**)&wvalT,  g_wvalT);
    cudaGetSymbolAddress((void**)&woutT,  g_woutT);
    cudaGetSymbolAddress((void**)&woaT,   g_woaT);
    cudaGetSymbolAddress((void**)&boa,    g_boa);

    // 1: everything independent — LNq, LNf, dest, weight prep
    misc_kernel<<<DEST_END, 256>>>(query, feat, mask,
                                   ln_q_s, ln_q_b, ln_f_s, ln_f_b,
                                   W_val, W_out, W_off, W_attn, b_off, b_attn,
                                   qbf, fbf, dest_s, wvalT, woutT, woaT, boa);

    // 2: value GEMM (43008x768x768 -> bf16) + oa GEMM (8192x384x768 -> f32)
    big_gemm<<<dim3(6, 336 + 64), 128>>>(fbf, wvalT, b_val, valb,
                                         qbf, woaT, boa, oa_s);

    // 3: sampling
    msda_sample_kernel<<<NQROWS, 128>>>(oa_s, valb, sampb);

    // 4: fused out GEMM: out[dest] = query + gamma*(samp @ W_out + b_out)
    out_gemm<<<dim3(6, NQROWS / 128), 128>>>(sampb, woutT, b_out, out,
                                             query, gamma, dest_s);
}

// round 16
// speedup vs baseline: 1.1977x; 1.0171x over previous
#include <cuda_runtime.h>
#include <cuda_bf16.h>
#include <cstdint>
#include <cstddef>

// ---------------------------------------------------------------------------
// SelectiveViTAdapter. 4 launches:
//   misc(LNq bf16 + LNf->int8+scale + Wval int8 quant + other prep + dest)
//   big_gemm(value GEMM int8 m16n8k32 + oa GEMM bf16, one launch)
//   sampler
//   out_gemm(bf16, fused residual+gamma+scatter)
// Round 16: value GEMM on int8 mma.sync m16n8k32 (2x FLOPs/instr vs bf16;
// s32 exact accumulation, per-row absmax scales). tensor pipe was issue-
// bound at 40% for bf16 mma regardless of config.
// ---------------------------------------------------------------------------

#define BATCH 8
#define DMODEL 768
#define NHEAD 6
#define DHEAD 128
#define LQ 1024
#define LIN 5376
#define NQROWS (BATCH * LQ)      // 8192
#define NFROWS (BATCH * LIN)     // 43008
#define OA_LD 384

// -------------------- scratch (static device globals) ----------------------
__device__ __nv_bfloat16 g_qbf[NQROWS * DMODEL];
__device__ int8_t        g_f8[NFROWS * DMODEL];      // int8 LN(f)
__device__ float         g_sfA[NFROWS];              // per-row scale of f8
__device__ __nv_bfloat16 g_valueb[NFROWS * DMODEL];
__device__ float         g_oa[NQROWS * OA_LD];
__device__ __nv_bfloat16 g_sampb[NQROWS * DMODEL];
__device__ int           g_dest[NQROWS];
__device__ int8_t        g_wval8[DMODEL * DMODEL];   // int8 W_val^T rows
__device__ float         g_sfB[DMODEL];              // per-n scale of wval8
__device__ __nv_bfloat16 g_woutT[DMODEL * DMODEL];
__device__ __nv_bfloat16 g_woaT[OA_LD * DMODEL];
__device__ float         g_boa[OA_LD];

// -------------------- PTX helpers ------------------------------------------
__device__ __forceinline__ uint32_t smem_u32(const void* p) {
    uint32_t a;
    asm("{ .reg .u64 t; cvta.to.shared.u64 t, %1; cvt.u32.u64 %0, t; }" : "=r"(a) : "l"(p));
    return a;
}
#define CP_ASYNC16(dst, src) asm volatile("cp.async.cg.shared.global [%0], [%1], 16;" :: "r"(dst), "l"(src) : "memory")
#define CP_COMMIT()          asm volatile("cp.async.commit_group;" ::: "memory")
#define CP_WAIT(n)           asm volatile("cp.async.wait_group %0;" :: "n"(n) : "memory")
#define LDSM4(r, a) asm volatile("ldmatrix.sync.aligned.m8n8.x4.shared.b16 {%0,%1,%2,%3}, [%4];" \
    : "=r"((r)[0]), "=r"((r)[1]), "=r"((r)[2]), "=r"((r)[3]) : "r"(a))

__device__ __forceinline__ void mma16816(float* c, const uint32_t* a, uint32_t b0, uint32_t b1) {
    asm volatile(
        "mma.sync.aligned.m16n8k16.row.col.f32.bf16.bf16.f32 "
        "{%0,%1,%2,%3}, {%4,%5,%6,%7}, {%8,%9}, {%0,%1,%2,%3};"
        : "+f"(c[0]), "+f"(c[1]), "+f"(c[2]), "+f"(c[3])
        : "r"(a[0]), "r"(a[1]), "r"(a[2]), "r"(a[3]), "r"(b0), "r"(b1));
}
__device__ __forceinline__ void mma16832_s8(int32_t* c, const uint32_t* a, uint32_t b0, uint32_t b1) {
    asm volatile(
        "mma.sync.aligned.m16n8k32.row.col.s32.s8.s8.s32 "
        "{%0,%1,%2,%3}, {%4,%5,%6,%7}, {%8,%9}, {%0,%1,%2,%3};"
        : "+r"(c[0]), "+r"(c[1]), "+r"(c[2]), "+r"(c[3])
        : "r"(a[0]), "r"(a[1]), "r"(a[2]), "r"(a[3]), "r"(b0), "r"(b1));
}
// bf16 tiles: 64B rows, 16B chunks c in [0,4)
__device__ __forceinline__ uint32_t sw_off(int r, int c) {
    return (uint32_t)(r * 64 + ((c ^ ((r >> 1) & 3)) << 4));
}
// int8 tiles: 32B rows, 16B chunks c in [0,2)
__device__ __forceinline__ uint32_t swi8(int r, int c) {
    return (uint32_t)(r * 32 + ((c ^ ((r >> 2) & 1)) << 4));
}

// -------------------- bf16 GEMM mainloop (3-stage, 4 warps, 64x64) ----------
__device__ __forceinline__ void gemm_mainloop(
    const __nv_bfloat16* __restrict__ Ag, const __nv_bfloat16* __restrict__ Bg,
    char* smbuf, float acc[4][8][4]) {
    uint32_t sb = smem_u32(smbuf);
    int tid = threadIdx.x, wid = tid >> 5, lane = tid & 31;
    int wm = (wid >> 1) * 64, wn = (wid & 1) * 64;
    int rb = tid >> 2, c4 = tid & 3;

    #pragma unroll
    for (int p = 0; p < 2; p++) {
        uint32_t stg = sb + (uint32_t)p * 16384;
        int k0 = p * 32;
        #pragma unroll
        for (int jj = 0; jj < 4; jj++) {
            int r = rb + jj * 32;
            uint32_t off = sw_off(r, c4);
            CP_ASYNC16(stg + off,        Ag + (size_t)r * DMODEL + k0 + c4 * 8);
            CP_ASYNC16(stg + 8192 + off, Bg + (size_t)r * DMODEL + k0 + c4 * 8);
        }
        CP_COMMIT();
    }

    int sidx = 0;
    for (int it = 0; it < 24; ++it) {
        if (it < 23) { CP_WAIT(1); } else { CP_WAIT(0); }
        __syncthreads();
        if (it + 2 < 24) {
            int ps = sidx + 2; if (ps >= 3) ps -= 3;
            uint32_t stg = sb + (uint32_t)ps * 16384;
            int k0 = (it + 2) * 32;
            #pragma unroll
            for (int jj = 0; jj < 4; jj++) {
                int r = rb + jj * 32;
                uint32_t off = sw_off(r, c4);
                CP_ASYNC16(stg + off,        Ag + (size_t)r * DMODEL + k0 + c4 * 8);
                CP_ASYNC16(stg + 8192 + off, Bg + (size_t)r * DMODEL + k0 + c4 * 8);
            }
            CP_COMMIT();
        }

        uint32_t aB = sb + (uint32_t)sidx * 16384;
        uint32_t bB = aB + 8192;
        #pragma unroll
        for (int ks = 0; ks < 2; ks++) {
            uint32_t ar[4][4], br[4][4];
            #pragma unroll
            for (int mi = 0; mi < 4; mi++) {
                int row = wm + mi * 16 + (lane & 15);
                int c = ks * 2 + (lane >> 4);
                LDSM4(ar[mi], aB + sw_off(row, c));
            }
            #pragma unroll
            for (int nb = 0; nb < 4; nb++) {
                int row = wn + nb * 16 + (lane & 7) + ((lane & 16) >> 1);
                int c = ks * 2 + ((lane & 8) >> 3);
                LDSM4(br[nb], bB + sw_off(row, c));
            }
            #pragma unroll
            for (int mi = 0; mi < 4; mi++)
                #pragma unroll
                for (int ni = 0; ni < 8; ni++)
                    mma16816(acc[mi][ni], ar[mi],
                             br[ni >> 1][(ni & 1) * 2], br[ni >> 1][(ni & 1) * 2 + 1]);
        }
        if (++sidx == 3) sidx = 0;
    }
}

// -------------------- int8 GEMM mainloop (3-stage, 4 warps, 64x64) ----------
// Stage 8KB (A 128x32B + B 128x32B). K=32 per iter, 24 iters.
__device__ __forceinline__ void gemm_i8_mainloop(
    const int8_t* __restrict__ Ag, const int8_t* __restrict__ Bg,
    char* smbuf, int32_t acc[4][8][4]) {
    uint32_t sb = smem_u32(smbuf);
    int tid = threadIdx.x, wid = tid >> 5, lane = tid & 31;
    int wm = (wid >> 1) * 64, wn = (wid & 1) * 64;
    uint32_t o0 = swi8(tid, 0), o1 = swi8(tid, 1);

    #pragma unroll
    for (int p = 0; p < 2; p++) {
        uint32_t stg = sb + (uint32_t)p * 8192;
        int k0 = p * 32;
        CP_ASYNC16(stg + o0,        Ag + (size_t)tid * DMODEL + k0);
        CP_ASYNC16(stg + o1,        Ag + (size_t)tid * DMODEL + k0 + 16);
        CP_ASYNC16(stg + 4096 + o0, Bg + (size_t)tid * DMODEL + k0);
        CP_ASYNC16(stg + 4096 + o1, Bg + (size_t)tid * DMODEL + k0 + 16);
        CP_COMMIT();
    }

    int sidx = 0;
    for (int it = 0; it < 24; ++it) {
        if (it < 23) { CP_WAIT(1); } else { CP_WAIT(0); }
        __syncthreads();
        if (it + 2 < 24) {
            int ps = sidx + 2; if (ps >= 3) ps -= 3;
            uint32_t stg = sb + (uint32_t)ps * 8192;
            int k0 = (it + 2) * 32;
            CP_ASYNC16(stg + o0,        Ag + (size_t)tid * DMODEL + k0);
            CP_ASYNC16(stg + o1,        Ag + (size_t)tid * DMODEL + k0 + 16);
            CP_ASYNC16(stg + 4096 + o0, Bg + (size_t)tid * DMODEL + k0);
            CP_ASYNC16(stg + 4096 + o1, Bg + (size_t)tid * DMODEL + k0 + 16);
            CP_COMMIT();
        }

        uint32_t aB = sb + (uint32_t)sidx * 8192;
        uint32_t bB = aB + 4096;
        uint32_t ar[4][4], br[4][4];
        // A frag (m16k32): lanes 0-7 m0(rows r..r+7,c0), 8-15 m1(rows+8,c0),
        //                  16-23 m2(rows,c1), 24-31 m3(rows+8,c1)
        #pragma unroll
        for (int mi = 0; mi < 4; mi++) {
            int row = wm + mi * 16 + ((lane >> 3) & 1) * 8 + (lane & 7);
            int c = lane >> 4;
            LDSM4(ar[mi], aB + swi8(row, c));
        }
        // B frag (k32n16 per nb): lanes 0-7 m0(n..n+7,c0), 8-15 m1(n..n+7,c1),
        //                         16-23 m2(n+8,c0), 24-31 m3(n+8,c1)
        #pragma unroll
        for (int nb = 0; nb < 4; nb++) {
            int row = wn + nb * 16 + (lane >> 4) * 8 + (lane & 7);
            int c = (lane >> 3) & 1;
            LDSM4(br[nb], bB + swi8(row, c));
        }
        #pragma unroll
        for (int mi = 0; mi < 4; mi++)
            #pragma unroll
            for (int ni = 0; ni < 8; ni++)
                mma16832_s8(acc[mi][ni], ar[mi],
                            br[ni >> 1][(ni & 1) * 2], br[ni >> 1][(ni & 1) * 2 + 1]);
        if (++sidx == 3) sidx = 0;
    }
}

// -------------------- big GEMM: int8 value + bf16 oa in one launch ----------
// blockIdx.y < 336: value tile (int8 -> dequant -> bf16 C, ldc 768)
// blockIdx.y >= 336 && blockIdx.x < 3: oa tile (bf16 -> f32 C, ldc 384)
__global__ __launch_bounds__(128) void big_gemm(
    const int8_t* __restrict__ A8, const int8_t* __restrict__ B8,
    const float* __restrict__ sA, const float* __restrict__ sB,
    const float* __restrict__ bv, __nv_bfloat16* __restrict__ Cv,
    const __nv_bfloat16* __restrict__ Aoa, const __nv_bfloat16* __restrict__ Boa,
    const float* __restrict__ boa, float* __restrict__ Coa) {
    __shared__ __align__(128) char smbuf[3 * 16384];
    int isOA = (blockIdx.y >= 336);
    if (isOA && blockIdx.x >= 3) return;
    int wid = threadIdx.x >> 5, lane = threadIdx.x & 31;
    int wm = (wid >> 1) * 64, wn = (wid & 1) * 64;

    if (!isOA) {
        int m0 = blockIdx.y * 128, n0 = blockIdx.x * 128;
        int32_t acc[4][8][4];
        #pragma unroll
        for (int i = 0; i < 4; i++)
            #pragma unroll
            for (int j = 0; j < 8; j++)
                #pragma unroll
                for (int k = 0; k < 4; k++) acc[i][j][k] = 0;
        gemm_i8_mainloop(A8 + (size_t)m0 * DMODEL, B8 + (size_t)n0 * DMODEL,
                         smbuf, acc);
        #pragma unroll
        for (int mi = 0; mi < 4; mi++) {
            int row = m0 + wm + mi * 16 + (lane >> 2);
            float a0 = sA[row], a1 = sA[row + 8];
            #pragma unroll
            for (int ni = 0; ni < 8; ni++) {
                int col = n0 + wn + ni * 8 + (lane & 3) * 2;
                float s0 = sB[col], s1 = sB[col + 1];
                float b0 = bv[col], b1 = bv[col + 1];
                __nv_bfloat162 v0 = __floats2bfloat162_rn(
                    (float)acc[mi][ni][0] * a0 * s0 + b0,
                    (float)acc[mi][ni][1] * a0 * s1 + b1);
                __nv_bfloat162 v1 = __floats2bfloat162_rn(
                    (float)acc[mi][ni][2] * a1 * s0 + b0,
                    (float)acc[mi][ni][3] * a1 * s1 + b1);
                *(__nv_bfloat162*)(Cv + (size_t)row * DMODEL + col) = v0;
                *(__nv_bfloat162*)(Cv + (size_t)(row + 8) * DMODEL + col) = v1;
            }
        }
    } else {
        int m0 = (blockIdx.y - 336) * 128, n0 = blockIdx.x * 128;
        float acc[4][8][4];
        #pragma unroll
        for (int i = 0; i < 4; i++)
            #pragma unroll
            for (int j = 0; j < 8; j++)
                #pragma unroll
                for (int k = 0; k < 4; k++) acc[i][j][k] = 0.f;
        gemm_mainloop(Aoa + (size_t)m0 * DMODEL, Boa + (size_t)n0 * DMODEL,
                      smbuf, acc);
        #pragma unroll
        for (int mi = 0; mi < 4; mi++) {
            int row = m0 + wm + mi * 16 + (lane >> 2);
            #pragma unroll
            for (int ni = 0; ni < 8; ni++) {
                int col = n0 + wn + ni * 8 + (lane & 3) * 2;
                float b0 = boa[col], b1 = boa[col + 1];
                float2 v0 = { acc[mi][ni][0] + b0, acc[mi][ni][1] + b1 };
                float2 v1 = { acc[mi][ni][2] + b0, acc[mi][ni][3] + b1 };
                *(float2*)(Coa + (size_t)row * OA_LD + col) = v0;
                *(float2*)(Coa + (size_t)(row + 8) * OA_LD + col) = v1;
            }
        }
    }
}

// -------------------- out GEMM: fused residual + scatter (bf16) -------------
__global__ __launch_bounds__(128) void out_gemm(
    const __nv_bfloat16* __restrict__ A, const __nv_bfloat16* __restrict__ Bt,
    const float* __restrict__ bias, float* __restrict__ C,
    const float* __restrict__ query, const float* __restrict__ gamma,
    const int* __restrict__ dest) {
    __shared__ __align__(128) char smbuf[3 * 16384];
    int m0 = blockIdx.y * 128, n0 = blockIdx.x * 128;
    float acc[4][8][4];
    #pragma unroll
    for (int i = 0; i < 4; i++)
        #pragma unroll
        for (int j = 0; j < 8; j++)
            #pragma unroll
            for (int k = 0; k < 4; k++) acc[i][j][k] = 0.f;
    gemm_mainloop(A + (size_t)m0 * DMODEL, Bt + (size_t)n0 * DMODEL, smbuf, acc);

    int wid = threadIdx.x >> 5, lane = threadIdx.x & 31;
    int wm = (wid >> 1) * 64, wn = (wid & 1) * 64;
    #pragma unroll
    for (int mi = 0; mi < 4; mi++) {
        int row = m0 + wm + mi * 16 + (lane >> 2);
        #pragma unroll
        for (int ni = 0; ni < 8; ni++) {
            int col = n0 + wn + ni * 8 + (lane & 3) * 2;
            float b0 = bias[col], b1 = bias[col + 1];
            float g0 = gamma[col], g1 = gamma[col + 1];
            int r0 = row, r1 = row + 8;
            int d0 = ((r0 >> 10) << 10) + dest[r0];
            int d1 = ((r1 >> 10) << 10) + dest[r1];
            float2 q0 = *(const float2*)(query + (size_t)r0 * DMODEL + col);
            float2 q1 = *(const float2*)(query + (size_t)r1 * DMODEL + col);
            float2 v0 = { q0.x + g0 * (acc[mi][ni][0] + b0),
                          q0.y + g1 * (acc[mi][ni][1] + b1) };
            float2 v1 = { q1.x + g0 * (acc[mi][ni][2] + b0),
                          q1.y + g1 * (acc[mi][ni][3] + b1) };
            *(float2*)(C + (size_t)d0 * DMODEL + col) = v0;
            *(float2*)(C + (size_t)d1 * DMODEL + col) = v1;
        }
    }
}

// -------------------- misc: LNq + LNf(int8) + Wval quant + prep + dest ------
#define LNQ_END 8192
#define LNF_END 51200                 // + NFROWS
#define WQ_END 51968                  // + 768 (W_val per-n quant)
#define PREP_END 55424                // + 1152*3 (wout 768 + woa 384 rows)
#define DEST_END 55432                // + 8

__device__ __forceinline__ float block_max(float m, float* sm8) {
    int t = threadIdx.x;
    #pragma unroll
    for (int o = 16; o > 0; o >>= 1)
        m = fmaxf(m, __shfl_xor_sync(0xffffffffu, m, o));
    if ((t & 31) == 0) sm8[t >> 5] = m;
    __syncthreads();
    float r = fmaxf(fmaxf(sm8[0], sm8[1]), fmaxf(sm8[2], sm8[3]));
    r = fmaxf(r, fmaxf(fmaxf(sm8[4], sm8[5]), fmaxf(sm8[6], sm8[7])));
    return r;
}
__device__ __forceinline__ int8_t q8(float v, float invs) {
    int q = __float2int_rn(v * invs);
    q = max(-127, min(127, q));
    return (int8_t)q;
}

__global__ __launch_bounds__(256) void misc_kernel(
    const float* __restrict__ query, const float* __restrict__ feat,
    const void* __restrict__ mraw,
    const float* __restrict__ ln_q_s, const float* __restrict__ ln_q_b,
    const float* __restrict__ ln_f_s, const float* __restrict__ ln_f_b,
    const float* __restrict__ Wv, const float* __restrict__ Wo,
    const float* __restrict__ Wf, const float* __restrict__ Wa,
    const float* __restrict__ boff, const float* __restrict__ batt,
    __nv_bfloat16* __restrict__ qbf,
    int8_t* __restrict__ f8, float* __restrict__ sfA,
    int8_t* __restrict__ wval8, float* __restrict__ sfB,
    int* __restrict__ dest,
    __nv_bfloat16* __restrict__ woutT,
    __nv_bfloat16* __restrict__ woaT, float* __restrict__ boa) {
    int bid = blockIdx.x;
    int t = threadIdx.x;
    __shared__ float ssum[8], ssq[8], sm8[8], smean, sinv;

    if (bid < LNQ_END) {   // LN(q) -> bf16
        const float* xr = query + (size_t)bid * DMODEL;
        float v0 = xr[t], v1 = xr[t + 256], v2 = xr[t + 512];
        float sum = v0 + v1 + v2, sq = v0 * v0 + v1 * v1 + v2 * v2;
        #pragma unroll
        for (int o = 16; o > 0; o >>= 1) {
            sum += __shfl_xor_sync(0xffffffffu, sum, o);
            sq  += __shfl_xor_sync(0xffffffffu, sq,  o);
        }
        if ((t & 31) == 0) { ssum[t >> 5] = sum; ssq[t >> 5] = sq; }
        __syncthreads();
        if (t == 0) {
            float S = 0.f, Q = 0.f;
            #pragma unroll
            for (int w = 0; w < 8; w++) { S += ssum[w]; Q += ssq[w]; }
            float mean = S * (1.0f / DMODEL);
            smean = mean;
            sinv = rsqrtf(Q * (1.0f / DMODEL) - mean * mean + 1e-6f);
        }
        __syncthreads();
        float mean = smean, inv = sinv;
        __nv_bfloat16* yr = qbf + (size_t)bid * DMODEL;
        yr[t]       = __float2bfloat16((v0 - mean) * inv * ln_q_s[t]       + ln_q_b[t]);
        yr[t + 256] = __float2bfloat16((v1 - mean) * inv * ln_q_s[t + 256] + ln_q_b[t + 256]);
        yr[t + 512] = __float2bfloat16((v2 - mean) * inv * ln_q_s[t + 512] + ln_q_b[t + 512]);
        return;
    }
    if (bid < LNF_END) {   // LN(f) -> int8 + per-row scale
        int row = bid - LNQ_END;
        const float* xr = feat + (size_t)row * DMODEL;
        float v0 = xr[t], v1 = xr[t + 256], v2 = xr[t + 512];
        float sum = v0 + v1 + v2, sq = v0 * v0 + v1 * v1 + v2 * v2;
        #pragma unroll
        for (int o = 16; o > 0; o >>= 1) {
            sum += __shfl_xor_sync(0xffffffffu, sum, o);
            sq  += __shfl_xor_sync(0xffffffffu, sq,  o);
        }
        if ((t & 31) == 0) { ssum[t >> 5] = sum; ssq[t >> 5] = sq; }
        __syncthreads();
        if (t == 0) {
            float S = 0.f, Q = 0.f;
            #pragma unroll
            for (int w = 0; w < 8; w++) { S += ssum[w]; Q += ssq[w]; }
            float mean = S * (1.0f / DMODEL);
            smean = mean;
            sinv = rsqrtf(Q * (1.0f / DMODEL) - mean * mean + 1e-6f);
        }
        __syncthreads();
        float mean = smean, inv = sinv;
        float y0 = (v0 - mean) * inv * ln_f_s[t]       + ln_f_b[t];
        float y1 = (v1 - mean) * inv * ln_f_s[t + 256] + ln_f_b[t + 256];
        float y2 = (v2 - mean) * inv * ln_f_s[t + 512] + ln_f_b[t + 512];
        float m = fmaxf(fabsf(y0), fmaxf(fabsf(y1), fabsf(y2)));
        float bm = block_max(m, sm8);
        float scale = (bm > 0.f) ? bm * (1.0f / 127.0f) : 1.f;
        float invs = 127.0f / fmaxf(bm, 1e-30f);
        if (bm <= 0.f) invs = 0.f;
        int8_t* yr = f8 + (size_t)row * DMODEL;
        yr[t]       = q8(y0, invs);
        yr[t + 256] = q8(y1, invs);
        yr[t + 512] = q8(y2, invs);
        if (t == 0) sfA[row] = scale;
        return;
    }
    if (bid < WQ_END) {    // W_val column n -> int8 row of wval8 + scale
        int n = bid - LNF_END;
        float w0 = Wv[(size_t)t * DMODEL + n];
        float w1 = Wv[(size_t)(t + 256) * DMODEL + n];
        float w2 = Wv[(size_t)(t + 512) * DMODEL + n];
        float m = fmaxf(fabsf(w0), fmaxf(fabsf(w1), fabsf(w2)));
        float bm = block_max(m, sm8);
        float scale = (bm > 0.f) ? bm * (1.0f / 127.0f) : 1.f;
        float invs = 127.0f / fmaxf(bm, 1e-30f);
        if (bm <= 0.f) invs = 0.f;
        int8_t* yr = wval8 + (size_t)n * DMODEL;
        yr[t]       = q8(w0, invs);
        yr[t + 256] = q8(w1, invs);
        yr[t + 512] = q8(w2, invs);
        if (t == 0) sfB[n] = scale;
        return;
    }
    if (bid < PREP_END) {  // wout / woa bf16 prep
        int pb = bid - WQ_END;           // 0..3455
        int r = pb % 1152;
        int k = (pb / 1152) * 256 + t;   // 0..767
        if (r < 768) {
            woutT[(size_t)r * DMODEL + k] = __float2bfloat16(Wo[(size_t)k * DMODEL + r]);
        } else if (r < 1024) {
            int n = r - 768;
            float v = (n < 144) ? Wf[(size_t)k * 144 + n] : 0.f;
            woaT[(size_t)n * DMODEL + k] = __float2bfloat16(v);
        } else {
            int n = r - 1024;
            float v = (n < 72) ? Wa[(size_t)k * 72 + n] : 0.f;
            woaT[(size_t)(256 + n) * DMODEL + k] = __float2bfloat16(v);
        }
        if (pb == 0) {
            boa[t] = (t < 144) ? boff[t] : 0.f;
            if (t < 128) boa[256 + t] = (t < 72) ? batt[t] : 0.f;
        }
        return;
    }
    {   // dest: one block per batch, 256 threads x 4 elements
        int b = bid - PREP_END;
        const unsigned char* mb = (const unsigned char*)mraw;
        __shared__ int flagA, flagB;
        __shared__ int s[256];
        if (t == 0) { flagA = 0; flagB = 0; }
        __syncthreads();
        int la = 0, lb = 0;
        for (int j = t; j < 8192; j += 256) {
            if (mb[j]) { if ((j & 3) == 0) la = 1; else lb = 1; }
        }
        if (la) atomicOr(&flagA, 1);
        if (lb) atomicOr(&flagB, 1);
        __syncthreads();
        int a = flagA, bbf = flagB;
        int base = b << 10;
        int m[4], cnt = 0;
        #pragma unroll
        for (int e = 0; e < 4; e++) {
            int idx = base + t * 4 + e;
            int mm;
            if (a && !bbf)      mm = (((const int*)mraw)[idx] != 0);
            else if (!a && bbf) mm = (((const float*)mraw)[idx] != 0.0f);
            else                mm = (mb[idx] != 0);
            m[e] = mm;
            cnt += mm;
        }
        s[t] = cnt;
        __syncthreads();
        for (int off = 1; off < 256; off <<= 1) {
            int v = (t >= off) ? s[t - off] : 0;
            __syncthreads();
            s[t] += v;
            __syncthreads();
        }
        int T = s[255];
        int run = s[t] - cnt;
        #pragma unroll
        for (int e = 0; e < 4; e++) {
            int i = t * 4 + e;
            if (m[e]) { dest[base + i] = run; run++; }
            else      { dest[base + i] = T + i - run; }
        }
    }
}

// -------------------- MSDeformAttn sampling (bf16 value) -------------------
__global__ __launch_bounds__(128) void msda_sample_kernel(
    const float* __restrict__ oa,
    const __nv_bfloat16* __restrict__ value,
    __nv_bfloat16* __restrict__ out) {
    __shared__ float sl[72];
    __shared__ float saw[72];
    __shared__ int   srow[72][4];
    __shared__ float swgt[72][4];

    int row = blockIdx.x;
    int b = row >> 10, q = row & 1023;
    int t = threadIdx.x;

    if (t < 72) sl[t] = oa[(size_t)row * OA_LD + 256 + t];
    __syncthreads();

    if (t < 6) {
        float mx = -1e30f;
        #pragma unroll
        for (int s = 0; s < 12; s++) mx = fmaxf(mx, sl[t * 12 + s]);
        float e[12], sum = 0.f;
        #pragma unroll
        for (int s = 0; s < 12; s++) { e[s] = expf(sl[t * 12 + s] - mx); sum += e[s]; }
        float inv = 1.f / sum;
        #pragma unroll
        for (int s = 0; s < 12; s++) saw[t * 12 + s] = e[s] * inv;
    }
    __syncthreads();

    if (t < 72) {
        int h = t / 12, s = t % 12, lvl = s >> 2, p = s & 3;
        const int DIMS[3] = {64, 32, 16};
        const int ST[3]   = {0, 4096, 5120};
        int Hd = DIMS[lvl], Wd = DIMS[lvl], st = ST[lvl];
        float refx = ((q & 31) + 0.5f) * (1.0f / 32.0f);
        float refy = ((q >> 5) + 0.5f) * (1.0f / 32.0f);
        size_t obase = (size_t)row * OA_LD + h * 24 + lvl * 8 + p * 2;
        float ox = oa[obase + 0];
        float oy = oa[obase + 1];
        float x = (refx + ox / (float)Wd) * (float)Wd - 0.5f;
        float y = (refy + oy / (float)Hd) * (float)Hd - 0.5f;
        float x0 = floorf(x), y0 = floorf(y);
        float wx1 = x - x0, wy1 = y - y0;
        int x0i = (int)x0, y0i = (int)y0;
        float aw = saw[t];
        #pragma unroll
        for (int c = 0; c < 4; c++) {
            int dx = c & 1, dy = c >> 1;
            int xi = x0i + dx, yi = y0i + dy;
            bool valid = (xi >= 0) && (xi < Wd) && (yi >= 0) && (yi < Hd);
            float wx = dx ? wx1 : 1.f - wx1;
            float wy = dy ? wy1 : 1.f - wy1;
            srow[t][c] = valid ? (st + yi * Wd + xi) : -1;
            swgt[t][c] = aw * wx * wy;
        }
    }
    __syncthreads();

    int d = t;
    const __nv_bfloat16* vb = value + (size_t)b * LIN * DMODEL + d;
    __nv_bfloat16* orow = out + (size_t)row * DMODEL + d;
    #pragma unroll 1
    for (int h = 0; h < NHEAD; h++) {
        float acc = 0.f;
        const __nv_bfloat16* vh = vb + h * DHEAD;
        #pragma unroll 1
        for (int s = 0; s < 12; s++) {
            int tt = h * 12 + s;
            #pragma unroll
            for (int c = 0; c < 4; c++) {
                int r = srow[tt][c];
                if (r >= 0) acc += swgt[tt][c] * __bfloat162float(vh[(size_t)r * DMODEL]);
            }
        }
        orow[h * DHEAD] = __float2bfloat16(acc);
    }
}

// -------------------- launch -----------------------------------------------
extern "C" void kernel_launch(void* const* d_in, const int* in_sizes, int n_in,
                              void* d_out, int out_size) {
    const float* query  = (const float*)d_in[0];
    const float* feat   = (const float*)d_in[1];
    const void*  mask   = d_in[2];
    const float* ln_q_s = (const float*)d_in[3];
    const float* ln_q_b = (const float*)d_in[4];
    const float* ln_f_s = (const float*)d_in[5];
    const float* ln_f_b = (const float*)d_in[6];
    const float* W_val  = (const float*)d_in[7];
    const float* b_val  = (const float*)d_in[8];
    const float* W_off  = (const float*)d_in[9];
    const float* b_off  = (const float*)d_in[10];
    const float* W_attn = (const float*)d_in[11];
    const float* b_attn = (const float*)d_in[12];
    const float* W_out  = (const float*)d_in[13];
    const float* b_out  = (const float*)d_in[14];
    const float* gamma  = (const float*)d_in[15];
    float* out = (float*)d_out;

    __nv_bfloat16 *qbf, *valb, *sampb, *woutT, *woaT;
    int8_t *f8, *wval8;
    float *sfA, *sfB, *oa_s, *boa;
    int* dest_s;
    cudaGetSymbolAddress((void**)&qbf,    g_qbf);
    cudaGetSymbolAddress((void**)&f8,     g_f8);
    cudaGetSymbolAddress((void**)&sfA,    g_sfA);
    cudaGetSymbolAddress((void**)&valb,   g_valueb);
    cudaGetSymbolAddress((void**)&oa_s,   g_oa);
    cudaGetSymbolAddress((void**)&sampb,  g_sampb);
    cudaGetSymbolAddress((void**)&dest_s, g_dest);
    cudaGetSymbolAddress((void**)&wval8,  g_wval8);
    cudaGetSymbolAddress((void**)&sfB,    g_sfB);
    cudaGetSymbolAddress((void**)&woutT,  g_woutT);
    cudaGetSymbolAddress((void**)&woaT,   g_woaT);
    cudaGetSymbolAddress((void**)&boa,    g_boa);

    // 1: LNq, LNf->int8, Wval quant, prep, dest
    misc_kernel<<<DEST_END, 256>>>(query, feat, mask,
                                   ln_q_s, ln_q_b, ln_f_s, ln_f_b,
                                   W_val, W_out, W_off, W_attn, b_off, b_attn,
                                   qbf, f8, sfA, wval8, sfB, dest_s,
                                   woutT, woaT, boa);

    // 2: value GEMM int8 (43008x768x768 -> bf16) + oa GEMM bf16 (8192x384x768)
    big_gemm<<<dim3(6, 336 + 64), 128>>>(f8, wval8, sfA, sfB, b_val, valb,
                                         qbf, woaT, boa, oa_s);

    // 3: sampling
    msda_sample_kernel<<<NQROWS, 128>>>(oa_s, valb, sampb);

    // 4: fused out GEMM: out[dest] = query + gamma*(samp @ W_out + b_out)
    out_gemm<<<dim3(6, NQROWS / 128), 128>>>(sampb, woutT, b_out, out,
                                             query, gamma, dest_s);
}

// round 17
// speedup vs baseline: 1.2741x; 1.0638x over previous
#include <cuda_runtime.h>
#include <cuda_bf16.h>
#include <cstdint>
#include <cstddef>

// ---------------------------------------------------------------------------
// SelectiveViTAdapter. 4 launches:
//   misc(LNq bf16 + LNf->int8+scale + Wval int8 quant + prep + dest)
//   big_gemm(value GEMM int8 m16n8k32 + oa GEMM bf16)
//   sampler (bf162-vectorized, 2 heads in parallel)
//   out_gemm(bf16, 64x128 tiles for wave-tail mitigation; fused residual+scatter)
// mma.sync is issue-capped ~220 TF/s on sm_100 regardless of dtype (measured);
// GEMM time is a floor — this round trims wave tails + sampler coalescing.
// ---------------------------------------------------------------------------

#define BATCH 8
#define DMODEL 768
#define NHEAD 6
#define DHEAD 128
#define LQ 1024
#define LIN 5376
#define NQROWS (BATCH * LQ)      // 8192
#define NFROWS (BATCH * LIN)     // 43008
#define OA_LD 384

// -------------------- scratch (static device globals) ----------------------
__device__ __nv_bfloat16 g_qbf[NQROWS * DMODEL];
__device__ int8_t        g_f8[NFROWS * DMODEL];
__device__ float         g_sfA[NFROWS];
__device__ __nv_bfloat16 g_valueb[NFROWS * DMODEL];
__device__ float         g_oa[NQROWS * OA_LD];
__device__ __nv_bfloat16 g_sampb[NQROWS * DMODEL];
__device__ int           g_dest[NQROWS];
__device__ int8_t        g_wval8[DMODEL * DMODEL];
__device__ float         g_sfB[DMODEL];
__device__ __nv_bfloat16 g_woutT[DMODEL * DMODEL];
__device__ __nv_bfloat16 g_woaT[OA_LD * DMODEL];
__device__ float         g_boa[OA_LD];

// -------------------- PTX helpers ------------------------------------------
__device__ __forceinline__ uint32_t smem_u32(const void* p) {
    uint32_t a;
    asm("{ .reg .u64 t; cvta.to.shared.u64 t, %1; cvt.u32.u64 %0, t; }" : "=r"(a) : "l"(p));
    return a;
}
#define CP_ASYNC16(dst, src) asm volatile("cp.async.cg.shared.global [%0], [%1], 16;" :: "r"(dst), "l"(src) : "memory")
#define CP_COMMIT()          asm volatile("cp.async.commit_group;" ::: "memory")
#define CP_WAIT(n)           asm volatile("cp.async.wait_group %0;" :: "n"(n) : "memory")
#define LDSM4(r, a) asm volatile("ldmatrix.sync.aligned.m8n8.x4.shared.b16 {%0,%1,%2,%3}, [%4];" \
    : "=r"((r)[0]), "=r"((r)[1]), "=r"((r)[2]), "=r"((r)[3]) : "r"(a))

__device__ __forceinline__ void mma16816(float* c, const uint32_t* a, uint32_t b0, uint32_t b1) {
    asm volatile(
        "mma.sync.aligned.m16n8k16.row.col.f32.bf16.bf16.f32 "
        "{%0,%1,%2,%3}, {%4,%5,%6,%7}, {%8,%9}, {%0,%1,%2,%3};"
        : "+f"(c[0]), "+f"(c[1]), "+f"(c[2]), "+f"(c[3])
        : "r"(a[0]), "r"(a[1]), "r"(a[2]), "r"(a[3]), "r"(b0), "r"(b1));
}
__device__ __forceinline__ void mma16832_s8(int32_t* c, const uint32_t* a, uint32_t b0, uint32_t b1) {
    asm volatile(
        "mma.sync.aligned.m16n8k32.row.col.s32.s8.s8.s32 "
        "{%0,%1,%2,%3}, {%4,%5,%6,%7}, {%8,%9}, {%0,%1,%2,%3};"
        : "+r"(c[0]), "+r"(c[1]), "+r"(c[2]), "+r"(c[3])
        : "r"(a[0]), "r"(a[1]), "r"(a[2]), "r"(a[3]), "r"(b0), "r"(b1));
}
// bf16 tiles: 64B rows, 16B chunks c in [0,4)
__device__ __forceinline__ uint32_t sw_off(int r, int c) {
    return (uint32_t)(r * 64 + ((c ^ ((r >> 1) & 3)) << 4));
}
// int8 tiles: 32B rows, 16B chunks c in [0,2)
__device__ __forceinline__ uint32_t swi8(int r, int c) {
    return (uint32_t)(r * 32 + ((c ^ ((r >> 2) & 1)) << 4));
}

// -------------------- bf16 GEMM mainloop (3-stage, 4 warps, 64x64) ----------
__device__ __forceinline__ void gemm_mainloop(
    const __nv_bfloat16* __restrict__ Ag, const __nv_bfloat16* __restrict__ Bg,
    char* smbuf, float acc[4][8][4]) {
    uint32_t sb = smem_u32(smbuf);
    int tid = threadIdx.x, wid = tid >> 5, lane = tid & 31;
    int wm = (wid >> 1) * 64, wn = (wid & 1) * 64;
    int rb = tid >> 2, c4 = tid & 3;

    #pragma unroll
    for (int p = 0; p < 2; p++) {
        uint32_t stg = sb + (uint32_t)p * 16384;
        int k0 = p * 32;
        #pragma unroll
        for (int jj = 0; jj < 4; jj++) {
            int r = rb + jj * 32;
            uint32_t off = sw_off(r, c4);
            CP_ASYNC16(stg + off,        Ag + (size_t)r * DMODEL + k0 + c4 * 8);
            CP_ASYNC16(stg + 8192 + off, Bg + (size_t)r * DMODEL + k0 + c4 * 8);
        }
        CP_COMMIT();
    }

    int sidx = 0;
    for (int it = 0; it < 24; ++it) {
        if (it < 23) { CP_WAIT(1); } else { CP_WAIT(0); }
        __syncthreads();
        if (it + 2 < 24) {
            int ps = sidx + 2; if (ps >= 3) ps -= 3;
            uint32_t stg = sb + (uint32_t)ps * 16384;
            int k0 = (it + 2) * 32;
            #pragma unroll
            for (int jj = 0; jj < 4; jj++) {
                int r = rb + jj * 32;
                uint32_t off = sw_off(r, c4);
                CP_ASYNC16(stg + off,        Ag + (size_t)r * DMODEL + k0 + c4 * 8);
                CP_ASYNC16(stg + 8192 + off, Bg + (size_t)r * DMODEL + k0 + c4 * 8);
            }
            CP_COMMIT();
        }

        uint32_t aB = sb + (uint32_t)sidx * 16384;
        uint32_t bB = aB + 8192;
        #pragma unroll
        for (int ks = 0; ks < 2; ks++) {
            uint32_t ar[4][4], br[4][4];
            #pragma unroll
            for (int mi = 0; mi < 4; mi++) {
                int row = wm + mi * 16 + (lane & 15);
                int c = ks * 2 + (lane >> 4);
                LDSM4(ar[mi], aB + sw_off(row, c));
            }
            #pragma unroll
            for (int nb = 0; nb < 4; nb++) {
                int row = wn + nb * 16 + (lane & 7) + ((lane & 16) >> 1);
                int c = ks * 2 + ((lane & 8) >> 3);
                LDSM4(br[nb], bB + sw_off(row, c));
            }
            #pragma unroll
            for (int mi = 0; mi < 4; mi++)
                #pragma unroll
                for (int ni = 0; ni < 8; ni++)
                    mma16816(acc[mi][ni], ar[mi],
                             br[ni >> 1][(ni & 1) * 2], br[ni >> 1][(ni & 1) * 2 + 1]);
        }
        if (++sidx == 3) sidx = 0;
    }
}

// -------------------- int8 GEMM mainloop (3-stage, 4 warps, 64x64) ----------
__device__ __forceinline__ void gemm_i8_mainloop(
    const int8_t* __restrict__ Ag, const int8_t* __restrict__ Bg,
    char* smbuf, int32_t acc[4][8][4]) {
    uint32_t sb = smem_u32(smbuf);
    int tid = threadIdx.x, wid = tid >> 5, lane = tid & 31;
    int wm = (wid >> 1) * 64, wn = (wid & 1) * 64;
    uint32_t o0 = swi8(tid, 0), o1 = swi8(tid, 1);

    #pragma unroll
    for (int p = 0; p < 2; p++) {
        uint32_t stg = sb + (uint32_t)p * 8192;
        int k0 = p * 32;
        CP_ASYNC16(stg + o0,        Ag + (size_t)tid * DMODEL + k0);
        CP_ASYNC16(stg + o1,        Ag + (size_t)tid * DMODEL + k0 + 16);
        CP_ASYNC16(stg + 4096 + o0, Bg + (size_t)tid * DMODEL + k0);
        CP_ASYNC16(stg + 4096 + o1, Bg + (size_t)tid * DMODEL + k0 + 16);
        CP_COMMIT();
    }

    int sidx = 0;
    for (int it = 0; it < 24; ++it) {
        if (it < 23) { CP_WAIT(1); } else { CP_WAIT(0); }
        __syncthreads();
        if (it + 2 < 24) {
            int ps = sidx + 2; if (ps >= 3) ps -= 3;
            uint32_t stg = sb + (uint32_t)ps * 8192;
            int k0 = (it + 2) * 32;
            CP_ASYNC16(stg + o0,        Ag + (size_t)tid * DMODEL + k0);
            CP_ASYNC16(stg + o1,        Ag + (size_t)tid * DMODEL + k0 + 16);
            CP_ASYNC16(stg + 4096 + o0, Bg + (size_t)tid * DMODEL + k0);
            CP_ASYNC16(stg + 4096 + o1, Bg + (size_t)tid * DMODEL + k0 + 16);
            CP_COMMIT();
        }

        uint32_t aB = sb + (uint32_t)sidx * 8192;
        uint32_t bB = aB + 4096;
        uint32_t ar[4][4], br[4][4];
        #pragma unroll
        for (int mi = 0; mi < 4; mi++) {
            int row = wm + mi * 16 + ((lane >> 3) & 1) * 8 + (lane & 7);
            int c = lane >> 4;
            LDSM4(ar[mi], aB + swi8(row, c));
        }
        #pragma unroll
        for (int nb = 0; nb < 4; nb++) {
            int row = wn + nb * 16 + (lane >> 4) * 8 + (lane & 7);
            int c = (lane >> 3) & 1;
            LDSM4(br[nb], bB + swi8(row, c));
        }
        #pragma unroll
        for (int mi = 0; mi < 4; mi++)
            #pragma unroll
            for (int ni = 0; ni < 8; ni++)
                mma16832_s8(acc[mi][ni], ar[mi],
                            br[ni >> 1][(ni & 1) * 2], br[ni >> 1][(ni & 1) * 2 + 1]);
        if (++sidx == 3) sidx = 0;
    }
}

// -------------------- big GEMM: int8 value + bf16 oa in one launch ----------
__global__ __launch_bounds__(128) void big_gemm(
    const int8_t* __restrict__ A8, const int8_t* __restrict__ B8,
    const float* __restrict__ sA, const float* __restrict__ sB,
    const float* __restrict__ bv, __nv_bfloat16* __restrict__ Cv,
    const __nv_bfloat16* __restrict__ Aoa, const __nv_bfloat16* __restrict__ Boa,
    const float* __restrict__ boa, float* __restrict__ Coa) {
    __shared__ __align__(128) char smbuf[3 * 16384];
    int isOA = (blockIdx.y >= 336);
    if (isOA && blockIdx.x >= 3) return;
    int wid = threadIdx.x >> 5, lane = threadIdx.x & 31;
    int wm = (wid >> 1) * 64, wn = (wid & 1) * 64;

    if (!isOA) {
        int m0 = blockIdx.y * 128, n0 = blockIdx.x * 128;
        int32_t acc[4][8][4];
        #pragma unroll
        for (int i = 0; i < 4; i++)
            #pragma unroll
            for (int j = 0; j < 8; j++)
                #pragma unroll
                for (int k = 0; k < 4; k++) acc[i][j][k] = 0;
        gemm_i8_mainloop(A8 + (size_t)m0 * DMODEL, B8 + (size_t)n0 * DMODEL,
                         smbuf, acc);
        #pragma unroll
        for (int mi = 0; mi < 4; mi++) {
            int row = m0 + wm + mi * 16 + (lane >> 2);
            float a0 = sA[row], a1 = sA[row + 8];
            #pragma unroll
            for (int ni = 0; ni < 8; ni++) {
                int col = n0 + wn + ni * 8 + (lane & 3) * 2;
                float s0 = sB[col], s1 = sB[col + 1];
                float b0 = bv[col], b1 = bv[col + 1];
                __nv_bfloat162 v0 = __floats2bfloat162_rn(
                    (float)acc[mi][ni][0] * a0 * s0 + b0,
                    (float)acc[mi][ni][1] * a0 * s1 + b1);
                __nv_bfloat162 v1 = __floats2bfloat162_rn(
                    (float)acc[mi][ni][2] * a1 * s0 + b0,
                    (float)acc[mi][ni][3] * a1 * s1 + b1);
                *(__nv_bfloat162*)(Cv + (size_t)row * DMODEL + col) = v0;
                *(__nv_bfloat162*)(Cv + (size_t)(row + 8) * DMODEL + col) = v1;
            }
        }
    } else {
        int m0 = (blockIdx.y - 336) * 128, n0 = blockIdx.x * 128;
        float acc[4][8][4];
        #pragma unroll
        for (int i = 0; i < 4; i++)
            #pragma unroll
            for (int j = 0; j < 8; j++)
                #pragma unroll
                for (int k = 0; k < 4; k++) acc[i][j][k] = 0.f;
        gemm_mainloop(Aoa + (size_t)m0 * DMODEL, Boa + (size_t)n0 * DMODEL,
                      smbuf, acc);
        #pragma unroll
        for (int mi = 0; mi < 4; mi++) {
            int row = m0 + wm + mi * 16 + (lane >> 2);
            #pragma unroll
            for (int ni = 0; ni < 8; ni++) {
                int col = n0 + wn + ni * 8 + (lane & 3) * 2;
                float b0 = boa[col], b1 = boa[col + 1];
                float2 v0 = { acc[mi][ni][0] + b0, acc[mi][ni][1] + b1 };
                float2 v1 = { acc[mi][ni][2] + b0, acc[mi][ni][3] + b1 };
                *(float2*)(Coa + (size_t)row * OA_LD + col) = v0;
                *(float2*)(Coa + (size_t)(row + 8) * OA_LD + col) = v1;
            }
        }
    }
}

// -------------------- out GEMM: 64x128 tiles, fused residual + scatter ------
// 4 warps as 2x2 grid of 32x64 warp tiles. Stage 12KB (A 4K + B 8K), 3 stages.
__global__ __launch_bounds__(128) void out_gemm(
    const __nv_bfloat16* __restrict__ A, const __nv_bfloat16* __restrict__ Bt,
    const float* __restrict__ bias, float* __restrict__ C,
    const float* __restrict__ query, const float* __restrict__ gamma,
    const int* __restrict__ dest) {
    __shared__ __align__(128) char smbuf[3 * 12288];
    uint32_t sb = smem_u32(smbuf);
    int tid = threadIdx.x, wid = tid >> 5, lane = tid & 31;
    int wm = (wid >> 1) * 32, wn = (wid & 1) * 64;
    int m0 = blockIdx.y * 64, n0 = blockIdx.x * 128;
    const __nv_bfloat16* Ag = A + (size_t)m0 * DMODEL;
    const __nv_bfloat16* Bg = Bt + (size_t)n0 * DMODEL;
    int rb = tid >> 2, c4 = tid & 3;     // A: rows 0..31 (+32), B: rows 0..31 (+32,64,96)

    float acc[2][8][4];
    #pragma unroll
    for (int i = 0; i < 2; i++)
        #pragma unroll
        for (int j = 0; j < 8; j++)
            #pragma unroll
            for (int k = 0; k < 4; k++) acc[i][j][k] = 0.f;

    #pragma unroll
    for (int p = 0; p < 2; p++) {
        uint32_t stg = sb + (uint32_t)p * 12288;
        int k0 = p * 32;
        #pragma unroll
        for (int jj = 0; jj < 2; jj++) {   // A: 64 rows
            int r = rb + jj * 32;
            CP_ASYNC16(stg + sw_off(r, c4), Ag + (size_t)r * DMODEL + k0 + c4 * 8);
        }
        #pragma unroll
        for (int jj = 0; jj < 4; jj++) {   // B: 128 rows
            int r = rb + jj * 32;
            CP_ASYNC16(stg + 4096 + sw_off(r, c4), Bg + (size_t)r * DMODEL + k0 + c4 * 8);
        }
        CP_COMMIT();
    }

    int sidx = 0;
    for (int it = 0; it < 24; ++it) {
        if (it < 23) { CP_WAIT(1); } else { CP_WAIT(0); }
        __syncthreads();
        if (it + 2 < 24) {
            int ps = sidx + 2; if (ps >= 3) ps -= 3;
            uint32_t stg = sb + (uint32_t)ps * 12288;
            int k0 = (it + 2) * 32;
            #pragma unroll
            for (int jj = 0; jj < 2; jj++) {
                int r = rb + jj * 32;
                CP_ASYNC16(stg + sw_off(r, c4), Ag + (size_t)r * DMODEL + k0 + c4 * 8);
            }
            #pragma unroll
            for (int jj = 0; jj < 4; jj++) {
                int r = rb + jj * 32;
                CP_ASYNC16(stg + 4096 + sw_off(r, c4), Bg + (size_t)r * DMODEL + k0 + c4 * 8);
            }
            CP_COMMIT();
        }

        uint32_t aB = sb + (uint32_t)sidx * 12288;
        uint32_t bB = aB + 4096;
        #pragma unroll
        for (int ks = 0; ks < 2; ks++) {
            uint32_t ar[2][4], br[4][4];
            #pragma unroll
            for (int mi = 0; mi < 2; mi++) {
                int row = wm + mi * 16 + (lane & 15);
                int c = ks * 2 + (lane >> 4);
                LDSM4(ar[mi], aB + sw_off(row, c));
            }
            #pragma unroll
            for (int nb = 0; nb < 4; nb++) {
                int row = wn + nb * 16 + (lane & 7) + ((lane & 16) >> 1);
                int c = ks * 2 + ((lane & 8) >> 3);
                LDSM4(br[nb], bB + sw_off(row, c));
            }
            #pragma unroll
            for (int mi = 0; mi < 2; mi++)
                #pragma unroll
                for (int ni = 0; ni < 8; ni++)
                    mma16816(acc[mi][ni], ar[mi],
                             br[ni >> 1][(ni & 1) * 2], br[ni >> 1][(ni & 1) * 2 + 1]);
        }
        if (++sidx == 3) sidx = 0;
    }

    #pragma unroll
    for (int mi = 0; mi < 2; mi++) {
        int row = m0 + wm + mi * 16 + (lane >> 2);
        #pragma unroll
        for (int ni = 0; ni < 8; ni++) {
            int col = n0 + wn + ni * 8 + (lane & 3) * 2;
            float b0 = bias[col], b1 = bias[col + 1];
            float g0 = gamma[col], g1 = gamma[col + 1];
            int r0 = row, r1 = row + 8;
            int d0 = ((r0 >> 10) << 10) + dest[r0];
            int d1 = ((r1 >> 10) << 10) + dest[r1];
            float2 q0 = *(const float2*)(query + (size_t)r0 * DMODEL + col);
            float2 q1 = *(const float2*)(query + (size_t)r1 * DMODEL + col);
            float2 v0 = { q0.x + g0 * (acc[mi][ni][0] + b0),
                          q0.y + g1 * (acc[mi][ni][1] + b1) };
            float2 v1 = { q1.x + g0 * (acc[mi][ni][2] + b0),
                          q1.y + g1 * (acc[mi][ni][3] + b1) };
            *(float2*)(C + (size_t)d0 * DMODEL + col) = v0;
            *(float2*)(C + (size_t)d1 * DMODEL + col) = v1;
        }
    }
}

// -------------------- misc: LNq + LNf(int8) + Wval quant + prep + dest ------
#define LNQ_END 8192
#define LNF_END 51200
#define WQ_END 51968
#define PREP_END 55424
#define DEST_END 55432

__device__ __forceinline__ float block_max(float m, float* sm8) {
    int t = threadIdx.x;
    #pragma unroll
    for (int o = 16; o > 0; o >>= 1)
        m = fmaxf(m, __shfl_xor_sync(0xffffffffu, m, o));
    if ((t & 31) == 0) sm8[t >> 5] = m;
    __syncthreads();
    float r = fmaxf(fmaxf(sm8[0], sm8[1]), fmaxf(sm8[2], sm8[3]));
    r = fmaxf(r, fmaxf(fmaxf(sm8[4], sm8[5]), fmaxf(sm8[6], sm8[7])));
    return r;
}
__device__ __forceinline__ int8_t q8(float v, float invs) {
    int q = __float2int_rn(v * invs);
    q = max(-127, min(127, q));
    return (int8_t)q;
}

__global__ __launch_bounds__(256) void misc_kernel(
    const float* __restrict__ query, const float* __restrict__ feat,
    const void* __restrict__ mraw,
    const float* __restrict__ ln_q_s, const float* __restrict__ ln_q_b,
    const float* __restrict__ ln_f_s, const float* __restrict__ ln_f_b,
    const float* __restrict__ Wv, const float* __restrict__ Wo,
    const float* __restrict__ Wf, const float* __restrict__ Wa,
    const float* __restrict__ boff, const float* __restrict__ batt,
    __nv_bfloat16* __restrict__ qbf,
    int8_t* __restrict__ f8, float* __restrict__ sfA,
    int8_t* __restrict__ wval8, float* __restrict__ sfB,
    int* __restrict__ dest,
    __nv_bfloat16* __restrict__ woutT,
    __nv_bfloat16* __restrict__ woaT, float* __restrict__ boa) {
    int bid = blockIdx.x;
    int t = threadIdx.x;
    __shared__ float ssum[8], ssq[8], sm8[8], smean, sinv;

    if (bid < LNQ_END) {
        const float* xr = query + (size_t)bid * DMODEL;
        float v0 = xr[t], v1 = xr[t + 256], v2 = xr[t + 512];
        float sum = v0 + v1 + v2, sq = v0 * v0 + v1 * v1 + v2 * v2;
        #pragma unroll
        for (int o = 16; o > 0; o >>= 1) {
            sum += __shfl_xor_sync(0xffffffffu, sum, o);
            sq  += __shfl_xor_sync(0xffffffffu, sq,  o);
        }
        if ((t & 31) == 0) { ssum[t >> 5] = sum; ssq[t >> 5] = sq; }
        __syncthreads();
        if (t == 0) {
            float S = 0.f, Q = 0.f;
            #pragma unroll
            for (int w = 0; w < 8; w++) { S += ssum[w]; Q += ssq[w]; }
            float mean = S * (1.0f / DMODEL);
            smean = mean;
            sinv = rsqrtf(Q * (1.0f / DMODEL) - mean * mean + 1e-6f);
        }
        __syncthreads();
        float mean = smean, inv = sinv;
        __nv_bfloat16* yr = qbf + (size_t)bid * DMODEL;
        yr[t]       = __float2bfloat16((v0 - mean) * inv * ln_q_s[t]       + ln_q_b[t]);
        yr[t + 256] = __float2bfloat16((v1 - mean) * inv * ln_q_s[t + 256] + ln_q_b[t + 256]);
        yr[t + 512] = __float2bfloat16((v2 - mean) * inv * ln_q_s[t + 512] + ln_q_b[t + 512]);
        return;
    }
    if (bid < LNF_END) {
        int row = bid - LNQ_END;
        const float* xr = feat + (size_t)row * DMODEL;
        float v0 = xr[t], v1 = xr[t + 256], v2 = xr[t + 512];
        float sum = v0 + v1 + v2, sq = v0 * v0 + v1 * v1 + v2 * v2;
        #pragma unroll
        for (int o = 16; o > 0; o >>= 1) {
            sum += __shfl_xor_sync(0xffffffffu, sum, o);
            sq  += __shfl_xor_sync(0xffffffffu, sq,  o);
        }
        if ((t & 31) == 0) { ssum[t >> 5] = sum; ssq[t >> 5] = sq; }
        __syncthreads();
        if (t == 0) {
            float S = 0.f, Q = 0.f;
            #pragma unroll
            for (int w = 0; w < 8; w++) { S += ssum[w]; Q += ssq[w]; }
            float mean = S * (1.0f / DMODEL);
            smean = mean;
            sinv = rsqrtf(Q * (1.0f / DMODEL) - mean * mean + 1e-6f);
        }
        __syncthreads();
        float mean = smean, inv = sinv;
        float y0 = (v0 - mean) * inv * ln_f_s[t]       + ln_f_b[t];
        float y1 = (v1 - mean) * inv * ln_f_s[t + 256] + ln_f_b[t + 256];
        float y2 = (v2 - mean) * inv * ln_f_s[t + 512] + ln_f_b[t + 512];
        float m = fmaxf(fabsf(y0), fmaxf(fabsf(y1), fabsf(y2)));
        float bm = block_max(m, sm8);
        float scale = (bm > 0.f) ? bm * (1.0f / 127.0f) : 1.f;
        float invs = 127.0f / fmaxf(bm, 1e-30f);
        if (bm <= 0.f) invs = 0.f;
        int8_t* yr = f8 + (size_t)row * DMODEL;
        yr[t]       = q8(y0, invs);
        yr[t + 256] = q8(y1, invs);
        yr[t + 512] = q8(y2, invs);
        if (t == 0) sfA[row] = scale;
        return;
    }
    if (bid < WQ_END) {
        int n = bid - LNF_END;
        float w0 = Wv[(size_t)t * DMODEL + n];
        float w1 = Wv[(size_t)(t + 256) * DMODEL + n];
        float w2 = Wv[(size_t)(t + 512) * DMODEL + n];
        float m = fmaxf(fabsf(w0), fmaxf(fabsf(w1), fabsf(w2)));
        float bm = block_max(m, sm8);
        float scale = (bm > 0.f) ? bm * (1.0f / 127.0f) : 1.f;
        float invs = 127.0f / fmaxf(bm, 1e-30f);
        if (bm <= 0.f) invs = 0.f;
        int8_t* yr = wval8 + (size_t)n * DMODEL;
        yr[t]       = q8(w0, invs);
        yr[t + 256] = q8(w1, invs);
        yr[t + 512] = q8(w2, invs);
        if (t == 0) sfB[n] = scale;
        return;
    }
    if (bid < PREP_END) {
        int pb = bid - WQ_END;
        int r = pb % 1152;
        int k = (pb / 1152) * 256 + t;
        if (r < 768) {
            woutT[(size_t)r * DMODEL + k] = __float2bfloat16(Wo[(size_t)k * DMODEL + r]);
        } else if (r < 1024) {
            int n = r - 768;
            float v = (n < 144) ? Wf[(size_t)k * 144 + n] : 0.f;
            woaT[(size_t)n * DMODEL + k] = __float2bfloat16(v);
        } else {
            int n = r - 1024;
            float v = (n < 72) ? Wa[(size_t)k * 72 + n] : 0.f;
            woaT[(size_t)(256 + n) * DMODEL + k] = __float2bfloat16(v);
        }
        if (pb == 0) {
            boa[t] = (t < 144) ? boff[t] : 0.f;
            if (t < 128) boa[256 + t] = (t < 72) ? batt[t] : 0.f;
        }
        return;
    }
    {
        int b = bid - PREP_END;
        const unsigned char* mb = (const unsigned char*)mraw;
        __shared__ int flagA, flagB;
        __shared__ int s[256];
        if (t == 0) { flagA = 0; flagB = 0; }
        __syncthreads();
        int la = 0, lb = 0;
        for (int j = t; j < 8192; j += 256) {
            if (mb[j]) { if ((j & 3) == 0) la = 1; else lb = 1; }
        }
        if (la) atomicOr(&flagA, 1);
        if (lb) atomicOr(&flagB, 1);
        __syncthreads();
        int a = flagA, bbf = flagB;
        int base = b << 10;
        int m[4], cnt = 0;
        #pragma unroll
        for (int e = 0; e < 4; e++) {
            int idx = base + t * 4 + e;
            int mm;
            if (a && !bbf)      mm = (((const int*)mraw)[idx] != 0);
            else if (!a && bbf) mm = (((const float*)mraw)[idx] != 0.0f);
            else                mm = (mb[idx] != 0);
            m[e] = mm;
            cnt += mm;
        }
        s[t] = cnt;
        __syncthreads();
        for (int off = 1; off < 256; off <<= 1) {
            int v = (t >= off) ? s[t - off] : 0;
            __syncthreads();
            s[t] += v;
            __syncthreads();
        }
        int T = s[255];
        int run = s[t] - cnt;
        #pragma unroll
        for (int e = 0; e < 4; e++) {
            int i = t * 4 + e;
            if (m[e]) { dest[base + i] = run; run++; }
            else      { dest[base + i] = T + i - run; }
        }
    }
}

// -------------------- MSDeformAttn sampling (bf162, 2 heads parallel) ------
__global__ __launch_bounds__(128) void msda_sample_kernel(
    const float* __restrict__ oa,
    const __nv_bfloat16* __restrict__ value,
    __nv_bfloat16* __restrict__ out) {
    __shared__ float sl[72];
    __shared__ float saw[72];
    __shared__ int   srow[72][4];
    __shared__ float swgt[72][4];

    int row = blockIdx.x;
    int b = row >> 10, q = row & 1023;
    int t = threadIdx.x;

    if (t < 72) sl[t] = oa[(size_t)row * OA_LD + 256 + t];
    __syncthreads();

    if (t < 6) {
        float mx = -1e30f;
        #pragma unroll
        for (int s = 0; s < 12; s++) mx = fmaxf(mx, sl[t * 12 + s]);
        float e[12], sum = 0.f;
        #pragma unroll
        for (int s = 0; s < 12; s++) { e[s] = expf(sl[t * 12 + s] - mx); sum += e[s]; }
        float inv = 1.f / sum;
        #pragma unroll
        for (int s = 0; s < 12; s++) saw[t * 12 + s] = e[s] * inv;
    }
    __syncthreads();

    if (t < 72) {
        int h = t / 12, s = t % 12, lvl = s >> 2, p = s & 3;
        const int DIMS[3] = {64, 32, 16};
        const int ST[3]   = {0, 4096, 5120};
        int Hd = DIMS[lvl], Wd = DIMS[lvl], st = ST[lvl];
        float refx = ((q & 31) + 0.5f) * (1.0f / 32.0f);
        float refy = ((q >> 5) + 0.5f) * (1.0f / 32.0f);
        size_t obase = (size_t)row * OA_LD + h * 24 + lvl * 8 + p * 2;
        float ox = oa[obase + 0];
        float oy = oa[obase + 1];
        float x = (refx + ox / (float)Wd) * (float)Wd - 0.5f;
        float y = (refy + oy / (float)Hd) * (float)Hd - 0.5f;
        float x0 = floorf(x), y0 = floorf(y);
        float wx1 = x - x0, wy1 = y - y0;
        int x0i = (int)x0, y0i = (int)y0;
        float aw = saw[t];
        #pragma unroll
        for (int c = 0; c < 4; c++) {
            int dx = c & 1, dy = c >> 1;
            int xi = x0i + dx, yi = y0i + dy;
            bool valid = (xi >= 0) && (xi < Wd) && (yi >= 0) && (yi < Hd);
            float wx = dx ? wx1 : 1.f - wx1;
            float wy = dy ? wy1 : 1.f - wy1;
            srow[t][c] = valid ? (st + yi * Wd + xi) : -1;
            swgt[t][c] = aw * wx * wy;
        }
    }
    __syncthreads();

    // threads: hh = t>>6 selects head parity, d2 = t&63 selects channel pair
    int hh = t >> 6, d2 = t & 63;
    const __nv_bfloat16* vb = value + (size_t)b * LIN * DMODEL;
    __nv_bfloat16* orow = out + (size_t)row * DMODEL;
    #pragma unroll 1
    for (int hbase = 0; hbase < NHEAD; hbase += 2) {
        int h = hbase + hh;
        int ch = h * DHEAD + d2 * 2;
        float ax = 0.f, ay = 0.f;
        #pragma unroll 1
        for (int s = 0; s < 12; s++) {
            int tt = h * 12 + s;
            #pragma unroll
            for (int c = 0; c < 4; c++) {
                int r = srow[tt][c];
                if (r >= 0) {
                    float w = swgt[tt][c];
                    __nv_bfloat162 v = *(const __nv_bfloat162*)(vb + (size_t)r * DMODEL + ch);
                    ax += w * __bfloat162float(v.x);
                    ay += w * __bfloat162float(v.y);
                }
            }
        }
        *(__nv_bfloat162*)(orow + ch) = __floats2bfloat162_rn(ax, ay);
    }
}

// -------------------- launch -----------------------------------------------
extern "C" void kernel_launch(void* const* d_in, const int* in_sizes, int n_in,
                              void* d_out, int out_size) {
    const float* query  = (const float*)d_in[0];
    const float* feat   = (const float*)d_in[1];
    const void*  mask   = d_in[2];
    const float* ln_q_s = (const float*)d_in[3];
    const float* ln_q_b = (const float*)d_in[4];
    const float* ln_f_s = (const float*)d_in[5];
    const float* ln_f_b = (const float*)d_in[6];
    const float* W_val  = (const float*)d_in[7];
    const float* b_val  = (const float*)d_in[8];
    const float* W_off  = (const float*)d_in[9];
    const float* b_off  = (const float*)d_in[10];
    const float* W_attn = (const float*)d_in[11];
    const float* b_attn = (const float*)d_in[12];
    const float* W_out  = (const float*)d_in[13];
    const float* b_out  = (const float*)d_in[14];
    const float* gamma  = (const float*)d_in[15];
    float* out = (float*)d_out;

    __nv_bfloat16 *qbf, *valb, *sampb, *woutT, *woaT;
    int8_t *f8, *wval8;
    float *sfA, *sfB, *oa_s, *boa;
    int* dest_s;
    cudaGetSymbolAddress((void**)&qbf,    g_qbf);
    cudaGetSymbolAddress((void**)&f8,     g_f8);
    cudaGetSymbolAddress((void**)&sfA,    g_sfA);
    cudaGetSymbolAddress((void**)&valb,   g_valueb);
    cudaGetSymbolAddress((void**)&oa_s,   g_oa);
    cudaGetSymbolAddress((void**)&sampb,  g_sampb);
    cudaGetSymbolAddress((void**)&dest_s, g_dest);
    cudaGetSymbolAddress((void**)&wval8,  g_wval8);
    cudaGetSymbolAddress((void**)&sfB,    g_sfB);
    cudaGetSymbolAddress((void**)&woutT,  g_woutT);
    cudaGetSymbolAddress((void**)&woaT,   g_woaT);
    cudaGetSymbolAddress((void**)&boa,    g_boa);

    // 1: LNq, LNf->int8, Wval quant, prep, dest
    misc_kernel<<<DEST_END, 256>>>(query, feat, mask,
                                   ln_q_s, ln_q_b, ln_f_s, ln_f_b,
                                   W_val, W_out, W_off, W_attn, b_off, b_attn,
                                   qbf, f8, sfA, wval8, sfB, dest_s,
                                   woutT, woaT, boa);

    // 2: value GEMM int8 + oa GEMM bf16
    big_gemm<<<dim3(6, 336 + 64), 128>>>(f8, wval8, sfA, sfB, b_val, valb,
                                         qbf, woaT, boa, oa_s);

    // 3: sampling
    msda_sample_kernel<<<NQROWS, 128>>>(oa_s, valb, sampb);

    // 4: out GEMM 64x128 tiles: out[dest] = query + gamma*(samp@W_out + b_out)
    out_gemm<<<dim3(6, NQROWS / 64), 128>>>(sampb, woutT, b_out, out,
                                            query, gamma, dest_s);
}